// round 1
// baseline (speedup 1.0000x reference)
#include <cuda_runtime.h>
#include <cuda_bf16.h>
#include <math.h>

#define B_DIM 2
#define T_DIM 2048
#define HID 2048
#define NH 16
#define NKV 4
#define HD 128
#define ROWS (B_DIM * T_DIM)          // 4096
#define QW (NH * HD)                  // 2048
#define KW (NKV * HD)                 // 512

// Scratch (device globals: allocation is forbidden)
__device__ float g_q[ROWS * QW];
__device__ float g_k[ROWS * KW];
__device__ float g_v[ROWS * KW];
__device__ float g_attn[ROWS * QW];

// ---------------------------------------------------------------------------
// Generic 128x128x8 register-blocked SGEMM: C[M,N] = A[M,K] @ B[K,N]
// M,N,K multiples of 128/128/8. 256 threads, 8x8 per thread.
// ---------------------------------------------------------------------------
__global__ __launch_bounds__(256) void sgemm128(
    const float* __restrict__ A, const float* __restrict__ B,
    float* __restrict__ C, int M, int N, int K)
{
    __shared__ float As[8][132];   // A^T tile: As[k][m]
    __shared__ float Bs[8][132];   // B tile:   Bs[k][n]

    const int tid = threadIdx.x;
    const int tx = tid & 15;       // 0..15 -> n
    const int ty = tid >> 4;       // 0..15 -> m
    const int bm = blockIdx.y * 128;
    const int bn = blockIdx.x * 128;

    const int arow = tid >> 1;            // 0..127
    const int acol = (tid & 1) * 4;       // 0 or 4
    const int brow = tid >> 5;            // 0..7
    const int bcol = (tid & 31) * 4;      // 0..124

    const float* Aptr = A + (size_t)(bm + arow) * K + acol;
    const float* Bptr = B + (size_t)brow * N + bn + bcol;

    float acc[8][8];
#pragma unroll
    for (int i = 0; i < 8; i++)
#pragma unroll
        for (int j = 0; j < 8; j++) acc[i][j] = 0.0f;

    for (int k0 = 0; k0 < K; k0 += 8) {
        float4 av = *(const float4*)(Aptr + k0);
        As[acol + 0][arow] = av.x;
        As[acol + 1][arow] = av.y;
        As[acol + 2][arow] = av.z;
        As[acol + 3][arow] = av.w;
        float4 bv = *(const float4*)(Bptr + (size_t)k0 * N);
        *(float4*)&Bs[brow][bcol] = bv;
        __syncthreads();

#pragma unroll
        for (int kk = 0; kk < 8; kk++) {
            float a_[8], b_[8];
            *(float4*)&a_[0] = *(const float4*)&As[kk][8 * ty];
            *(float4*)&a_[4] = *(const float4*)&As[kk][8 * ty + 4];
            *(float4*)&b_[0] = *(const float4*)&Bs[kk][8 * tx];
            *(float4*)&b_[4] = *(const float4*)&Bs[kk][8 * tx + 4];
#pragma unroll
            for (int i = 0; i < 8; i++)
#pragma unroll
                for (int j = 0; j < 8; j++)
                    acc[i][j] = fmaf(a_[i], b_[j], acc[i][j]);
        }
        __syncthreads();
    }

    float* Cp = C + (size_t)(bm + 8 * ty) * N + bn + 8 * tx;
#pragma unroll
    for (int i = 0; i < 8; i++) {
        *(float4*)(Cp + (size_t)i * N)     = make_float4(acc[i][0], acc[i][1], acc[i][2], acc[i][3]);
        *(float4*)(Cp + (size_t)i * N + 4) = make_float4(acc[i][4], acc[i][5], acc[i][6], acc[i][7]);
    }
}

// ---------------------------------------------------------------------------
// RoPE in-place on [ROWS][heads*HD] buffer. One thread per (row, head, d<64).
// ---------------------------------------------------------------------------
__global__ void rope_kernel(float* __restrict__ t,
                            const float* __restrict__ cosb,
                            const float* __restrict__ sinb,
                            int heads)
{
    int idx = blockIdx.x * blockDim.x + threadIdx.x;
    int total = ROWS * heads * (HD / 2);
    if (idx >= total) return;
    int d = idx & 63;
    int h = (idx >> 6) % heads;
    int row = idx / (64 * heads);
    int tpos = row & (T_DIM - 1);

    const float c1 = cosb[tpos * HD + d];
    const float s1 = sinb[tpos * HD + d];
    const float c2 = cosb[tpos * HD + d + 64];
    const float s2 = sinb[tpos * HD + d + 64];

    float* p = t + (size_t)row * heads * HD + h * HD;
    float x1 = p[d];
    float x2 = p[d + 64];
    p[d]      = x1 * c1 - x2 * s1;   // first half: t*cos + (-t2)*sin
    p[d + 64] = x2 * c2 + x1 * s2;   // second half: t*cos + t1*sin
}

// ---------------------------------------------------------------------------
// fp32 flash attention, causal, GQA. 64x64 tiles, 256 threads (16x16),
// each thread: 4 q-rows x 4 score-cols / 8 out-cols.
// ---------------------------------------------------------------------------
#define FBM 64
#define FBN 64
#define QS_STRIDE 129
#define VS_STRIDE 132
#define PS_STRIDE 65
#define FLASH_SMEM_FLOATS (64*QS_STRIDE*2 + 64*VS_STRIDE + 64*PS_STRIDE)
#define FLASH_SMEM_BYTES (FLASH_SMEM_FLOATS * 4)

__global__ __launch_bounds__(256) void flash_attn(
    const float* __restrict__ q, const float* __restrict__ k,
    const float* __restrict__ v, float* __restrict__ o)
{
    extern __shared__ float sm[];
    float* Qs = sm;                      // [64][129]
    float* Ks = Qs + 64 * QS_STRIDE;     // [64][129]
    float* Vs = Ks + 64 * QS_STRIDE;     // [64][132]
    float* Ps = Vs + 64 * VS_STRIDE;     // [64][65]

    const int tid = threadIdx.x;
    const int tx = tid & 15;
    const int ty = tid >> 4;
    const int i0 = blockIdx.x * FBM;
    const int h  = blockIdx.y;
    const int b  = blockIdx.z;
    const int kh = h >> 2;               // GQA: 4 q-heads per kv-head

    const float* qbase = q + ((size_t)b * T_DIM) * QW + h * HD;
    const float* kbase = k + ((size_t)b * T_DIM) * KW + kh * HD;
    const float* vbase = v + ((size_t)b * T_DIM) * KW + kh * HD;

    const float scale = 0.08838834764831845f;   // 1/sqrt(128)

    // Load Q tile (pre-scaled), transposed-free layout Qs[row][d]
    {
        int f  = tid & 31;    // d quad: d = 4f
        int r0 = tid >> 5;    // 0..7
#pragma unroll
        for (int i = 0; i < 8; i++) {
            int lr = r0 + 8 * i;
            float4 val = *(const float4*)(qbase + (size_t)(i0 + lr) * QW + 4 * f);
            float* dst = Qs + lr * QS_STRIDE + 4 * f;
            dst[0] = val.x * scale; dst[1] = val.y * scale;
            dst[2] = val.z * scale; dst[3] = val.w * scale;
        }
    }

    float m_i[4], l_i[4], O[4][8];
#pragma unroll
    for (int i = 0; i < 4; i++) {
        m_i[i] = -INFINITY;
        l_i[i] = 0.0f;
#pragma unroll
        for (int j = 0; j < 8; j++) O[i][j] = 0.0f;
    }

    const int ntiles = i0 / FBN + 1;
    for (int jt = 0; jt < ntiles; jt++) {
        const int j0 = jt * FBN;
        __syncthreads();   // protect prior Ks/Vs/Ps reads
        {
            int f  = tid & 31;
            int r0 = tid >> 5;
#pragma unroll
            for (int i = 0; i < 8; i++) {
                int lr = r0 + 8 * i;
                float4 kv4 = *(const float4*)(kbase + (size_t)(j0 + lr) * KW + 4 * f);
                float* kd = Ks + lr * QS_STRIDE + 4 * f;
                kd[0] = kv4.x; kd[1] = kv4.y; kd[2] = kv4.z; kd[3] = kv4.w;
                float4 vv4 = *(const float4*)(vbase + (size_t)(j0 + lr) * KW + 4 * f);
                *(float4*)(Vs + lr * VS_STRIDE + 4 * f) = vv4;
            }
        }
        __syncthreads();

        // S = Qs @ Ks^T  (Q pre-scaled)
        float S[4][4];
#pragma unroll
        for (int i = 0; i < 4; i++)
#pragma unroll
            for (int j = 0; j < 4; j++) S[i][j] = 0.0f;

#pragma unroll 4
        for (int d = 0; d < HD; d++) {
            float a_[4], b_[4];
#pragma unroll
            for (int i = 0; i < 4; i++) a_[i] = Qs[(4 * ty + i) * QS_STRIDE + d];
#pragma unroll
            for (int j = 0; j < 4; j++) b_[j] = Ks[(4 * tx + j) * QS_STRIDE + d];
#pragma unroll
            for (int i = 0; i < 4; i++)
#pragma unroll
                for (int j = 0; j < 4; j++)
                    S[i][j] = fmaf(a_[i], b_[j], S[i][j]);
        }

        // causal mask (only the diagonal tile needs it: BM == BN)
        if (j0 == i0) {
#pragma unroll
            for (int i = 0; i < 4; i++)
#pragma unroll
                for (int j = 0; j < 4; j++)
                    if ((j0 + 4 * tx + j) > (i0 + 4 * ty + i)) S[i][j] = -1e30f;
        }

        // online softmax per row (rows shared by 16 tx-threads in same half-warp)
#pragma unroll
        for (int i = 0; i < 4; i++) {
            float rm = fmaxf(fmaxf(S[i][0], S[i][1]), fmaxf(S[i][2], S[i][3]));
#pragma unroll
            for (int off = 1; off < 16; off <<= 1)
                rm = fmaxf(rm, __shfl_xor_sync(0xffffffffu, rm, off));
            float m_new = fmaxf(m_i[i], rm);
            float alpha = __expf(m_i[i] - m_new);
            float p[4], rs = 0.0f;
#pragma unroll
            for (int j = 0; j < 4; j++) { p[j] = __expf(S[i][j] - m_new); rs += p[j]; }
#pragma unroll
            for (int off = 1; off < 16; off <<= 1)
                rs += __shfl_xor_sync(0xffffffffu, rs, off);
            l_i[i] = l_i[i] * alpha + rs;
            m_i[i] = m_new;
#pragma unroll
            for (int j = 0; j < 8; j++) O[i][j] *= alpha;
#pragma unroll
            for (int j = 0; j < 4; j++)
                Ps[(4 * ty + i) * PS_STRIDE + 4 * tx + j] = p[j];
        }
        __syncthreads();

        // O += P @ V
#pragma unroll 2
        for (int s = 0; s < FBN; s++) {
            float p0 = Ps[(4 * ty + 0) * PS_STRIDE + s];
            float p1 = Ps[(4 * ty + 1) * PS_STRIDE + s];
            float p2 = Ps[(4 * ty + 2) * PS_STRIDE + s];
            float p3 = Ps[(4 * ty + 3) * PS_STRIDE + s];
            float4 v0 = *(const float4*)(Vs + s * VS_STRIDE + 8 * tx);
            float4 v1 = *(const float4*)(Vs + s * VS_STRIDE + 8 * tx + 4);
            O[0][0] = fmaf(p0, v0.x, O[0][0]); O[0][1] = fmaf(p0, v0.y, O[0][1]);
            O[0][2] = fmaf(p0, v0.z, O[0][2]); O[0][3] = fmaf(p0, v0.w, O[0][3]);
            O[0][4] = fmaf(p0, v1.x, O[0][4]); O[0][5] = fmaf(p0, v1.y, O[0][5]);
            O[0][6] = fmaf(p0, v1.z, O[0][6]); O[0][7] = fmaf(p0, v1.w, O[0][7]);
            O[1][0] = fmaf(p1, v0.x, O[1][0]); O[1][1] = fmaf(p1, v0.y, O[1][1]);
            O[1][2] = fmaf(p1, v0.z, O[1][2]); O[1][3] = fmaf(p1, v0.w, O[1][3]);
            O[1][4] = fmaf(p1, v1.x, O[1][4]); O[1][5] = fmaf(p1, v1.y, O[1][5]);
            O[1][6] = fmaf(p1, v1.z, O[1][6]); O[1][7] = fmaf(p1, v1.w, O[1][7]);
            O[2][0] = fmaf(p2, v0.x, O[2][0]); O[2][1] = fmaf(p2, v0.y, O[2][1]);
            O[2][2] = fmaf(p2, v0.z, O[2][2]); O[2][3] = fmaf(p2, v0.w, O[2][3]);
            O[2][4] = fmaf(p2, v1.x, O[2][4]); O[2][5] = fmaf(p2, v1.y, O[2][5]);
            O[2][6] = fmaf(p2, v1.z, O[2][6]); O[2][7] = fmaf(p2, v1.w, O[2][7]);
            O[3][0] = fmaf(p3, v0.x, O[3][0]); O[3][1] = fmaf(p3, v0.y, O[3][1]);
            O[3][2] = fmaf(p3, v0.z, O[3][2]); O[3][3] = fmaf(p3, v0.w, O[3][3]);
            O[3][4] = fmaf(p3, v1.x, O[3][4]); O[3][5] = fmaf(p3, v1.y, O[3][5]);
            O[3][6] = fmaf(p3, v1.z, O[3][6]); O[3][7] = fmaf(p3, v1.w, O[3][7]);
        }
    }

    // epilogue: normalize and write [b,t][h*HD + d]
    float* obase = o + ((size_t)(b * T_DIM + i0)) * QW + h * HD;
#pragma unroll
    for (int i = 0; i < 4; i++) {
        float inv = 1.0f / l_i[i];
        float4 w0 = make_float4(O[i][0] * inv, O[i][1] * inv, O[i][2] * inv, O[i][3] * inv);
        float4 w1 = make_float4(O[i][4] * inv, O[i][5] * inv, O[i][6] * inv, O[i][7] * inv);
        *(float4*)(obase + (size_t)(4 * ty + i) * QW + 8 * tx)     = w0;
        *(float4*)(obase + (size_t)(4 * ty + i) * QW + 8 * tx + 4) = w1;
    }
}

// ---------------------------------------------------------------------------
extern "C" void kernel_launch(void* const* d_in, const int* in_sizes, int n_in,
                              void* d_out, int out_size)
{
    const float* x    = (const float*)d_in[0];
    const float* cosb = (const float*)d_in[1];
    const float* sinb = (const float*)d_in[2];
    const float* Wq   = (const float*)d_in[3];
    const float* Wk   = (const float*)d_in[4];
    const float* Wv   = (const float*)d_in[5];
    const float* Wo   = (const float*)d_in[6];
    float* out = (float*)d_out;

    float *qp, *kp, *vp, *ap;
    cudaGetSymbolAddress((void**)&qp, g_q);
    cudaGetSymbolAddress((void**)&kp, g_k);
    cudaGetSymbolAddress((void**)&vp, g_v);
    cudaGetSymbolAddress((void**)&ap, g_attn);

    cudaFuncSetAttribute(flash_attn, cudaFuncAttributeMaxDynamicSharedMemorySize,
                         FLASH_SMEM_BYTES);

    // Projections
    sgemm128<<<dim3(QW / 128, ROWS / 128), 256>>>(x, Wq, qp, ROWS, QW, HID);
    sgemm128<<<dim3(KW / 128, ROWS / 128), 256>>>(x, Wk, kp, ROWS, KW, HID);
    sgemm128<<<dim3(KW / 128, ROWS / 128), 256>>>(x, Wv, vp, ROWS, KW, HID);

    // RoPE on q and k
    {
        int totq = ROWS * NH * (HD / 2);
        rope_kernel<<<(totq + 255) / 256, 256>>>(qp, cosb, sinb, NH);
        int totk = ROWS * NKV * (HD / 2);
        rope_kernel<<<(totk + 255) / 256, 256>>>(kp, cosb, sinb, NKV);
    }

    // Attention
    flash_attn<<<dim3(T_DIM / FBM, NH, B_DIM), 256, FLASH_SMEM_BYTES>>>(qp, kp, vp, ap);

    // Output projection
    sgemm128<<<dim3(HID / 128, ROWS / 128), 256>>>(ap, Wo, out, ROWS, HID, HID);
}

// round 2
// speedup vs baseline: 1.0259x; 1.0259x over previous
#include <cuda_runtime.h>
#include <cuda_bf16.h>
#include <math.h>
#include <stdint.h>

#define B_DIM 2
#define T_DIM 2048
#define HID 2048
#define NH 16
#define NKV 4
#define HD 128
#define ROWS (B_DIM * T_DIM)          // 4096
#define QW (NH * HD)                  // 2048
#define KW (NKV * HD)                 // 512

// Scratch (device globals: allocation is forbidden)
__device__ float g_q[ROWS * QW];
__device__ float g_k[ROWS * KW];
__device__ float g_v[ROWS * KW];
__device__ float g_attn[ROWS * QW];

// ---------------------------------------------------------------------------
// tf32 tensor-core GEMM: C[M,N] = A[M,K] @ B[K,N]
// 128x128x16 block tile, 8 warps (2x4), warp tile 64x32, mma.m16n8k8.tf32.
// ---------------------------------------------------------------------------
#define GBM 128
#define GBN 128
#define GBK 16
#define GST 136   // smem row stride: 8k+n mod 32 distinct -> conflict-free frags

__device__ __forceinline__ float to_tf32(float x) {
    float r;
    asm("cvt.rna.tf32.f32 %0, %1;" : "=f"(r) : "f"(x));
    return r;
}

__device__ __forceinline__ void mma_tf32(float* d, const uint32_t* a, const uint32_t* b) {
    asm volatile(
        "mma.sync.aligned.m16n8k8.row.col.f32.tf32.tf32.f32 "
        "{%0,%1,%2,%3}, {%4,%5,%6,%7}, {%8,%9}, {%0,%1,%2,%3};"
        : "+f"(d[0]), "+f"(d[1]), "+f"(d[2]), "+f"(d[3])
        : "r"(a[0]), "r"(a[1]), "r"(a[2]), "r"(a[3]), "r"(b[0]), "r"(b[1]));
}

__global__ __launch_bounds__(256, 2) void gemm_tf32(
    const float* __restrict__ A, const float* __restrict__ B,
    float* __restrict__ C, int M, int N, int K)
{
    __shared__ float As[GBK][GST];   // As[k][m]
    __shared__ float Bs[GBK][GST];   // Bs[k][n]

    const int tid  = threadIdx.x;
    const int lane = tid & 31;
    const int warp = tid >> 5;
    const int wm = (warp >> 2) * 64;   // warp row offset in tile
    const int wn = (warp & 3) * 32;    // warp col offset in tile
    const int bm = blockIdx.y * GBM;
    const int bn = blockIdx.x * GBN;

    // A load: thread covers A[bm+am][ak .. ak+7]
    const int am = tid >> 1;
    const int ak = (tid & 1) * 8;
    // B load: thread covers B[bk][bn+bn8 .. +7]
    const int bk  = tid >> 4;
    const int bn8 = (tid & 15) * 8;

    const float* Ap = A + (size_t)(bm + am) * K + ak;
    const float* Bp = B + (size_t)bk * N + bn + bn8;

    float acc[4][4][4];
#pragma unroll
    for (int mi = 0; mi < 4; mi++)
#pragma unroll
        for (int ni = 0; ni < 4; ni++)
#pragma unroll
            for (int r = 0; r < 4; r++) acc[mi][ni][r] = 0.0f;

    float pa[8], pb[8];
    // prefetch tile 0
    *(float4*)&pa[0] = *(const float4*)(Ap);
    *(float4*)&pa[4] = *(const float4*)(Ap + 4);
    *(float4*)&pb[0] = *(const float4*)(Bp);
    *(float4*)&pb[4] = *(const float4*)(Bp + 4);

    const int ntiles = K / GBK;
    for (int t = 0; t < ntiles; t++) {
        // store prefetched tile to smem (convert to tf32 here)
#pragma unroll
        for (int i = 0; i < 8; i++) As[ak + i][am] = to_tf32(pa[i]);
#pragma unroll
        for (int i = 0; i < 8; i++) Bs[bk][bn8 + i] = to_tf32(pb[i]);
        __syncthreads();

        if (t + 1 < ntiles) {
            const float* An = Ap + (size_t)(t + 1) * GBK;
            const float* Bn = Bp + (size_t)(t + 1) * GBK * N;
            *(float4*)&pa[0] = *(const float4*)(An);
            *(float4*)&pa[4] = *(const float4*)(An + 4);
            *(float4*)&pb[0] = *(const float4*)(Bn);
            *(float4*)&pb[4] = *(const float4*)(Bn + 4);
        }

#pragma unroll
        for (int ks = 0; ks < 2; ks++) {
            const int k0 = ks * 8 + (lane & 3);
            uint32_t af[4][4], bf[4][2];
#pragma unroll
            for (int mi = 0; mi < 4; mi++) {
                const int row = wm + mi * 16 + (lane >> 2);
                af[mi][0] = __float_as_uint(As[k0][row]);
                af[mi][1] = __float_as_uint(As[k0][row + 8]);
                af[mi][2] = __float_as_uint(As[k0 + 4][row]);
                af[mi][3] = __float_as_uint(As[k0 + 4][row + 8]);
            }
#pragma unroll
            for (int ni = 0; ni < 4; ni++) {
                const int col = wn + ni * 8 + (lane >> 2);
                bf[ni][0] = __float_as_uint(Bs[k0][col]);
                bf[ni][1] = __float_as_uint(Bs[k0 + 4][col]);
            }
#pragma unroll
            for (int mi = 0; mi < 4; mi++)
#pragma unroll
                for (int ni = 0; ni < 4; ni++)
                    mma_tf32(acc[mi][ni], af[mi], bf[ni]);
        }
        __syncthreads();
    }

    // epilogue
#pragma unroll
    for (int mi = 0; mi < 4; mi++) {
#pragma unroll
        for (int ni = 0; ni < 4; ni++) {
            const int row = bm + wm + mi * 16 + (lane >> 2);
            const int col = bn + wn + ni * 8 + (lane & 3) * 2;
            *(float2*)&C[(size_t)row * N + col] =
                make_float2(acc[mi][ni][0], acc[mi][ni][1]);
            *(float2*)&C[(size_t)(row + 8) * N + col] =
                make_float2(acc[mi][ni][2], acc[mi][ni][3]);
        }
    }
}

// ---------------------------------------------------------------------------
// RoPE in-place on [ROWS][heads*HD] buffer. One thread per (row, head, d<64).
// ---------------------------------------------------------------------------
__global__ void rope_kernel(float* __restrict__ t,
                            const float* __restrict__ cosb,
                            const float* __restrict__ sinb,
                            int heads)
{
    int idx = blockIdx.x * blockDim.x + threadIdx.x;
    int total = ROWS * heads * (HD / 2);
    if (idx >= total) return;
    int d = idx & 63;
    int h = (idx >> 6) % heads;
    int row = idx / (64 * heads);
    int tpos = row & (T_DIM - 1);

    const float c1 = cosb[tpos * HD + d];
    const float s1 = sinb[tpos * HD + d];
    const float c2 = cosb[tpos * HD + d + 64];
    const float s2 = sinb[tpos * HD + d + 64];

    float* p = t + (size_t)row * heads * HD + h * HD;
    float x1 = p[d];
    float x2 = p[d + 64];
    p[d]      = x1 * c1 - x2 * s1;
    p[d + 64] = x2 * c2 + x1 * s2;
}

// ---------------------------------------------------------------------------
// fp32 flash attention, causal, GQA. 64x64 tiles, 256 threads (16x16).
// ---------------------------------------------------------------------------
#define FBM 64
#define FBN 64
#define QS_STRIDE 129
#define VS_STRIDE 132
#define PS_STRIDE 65
#define FLASH_SMEM_FLOATS (64*QS_STRIDE*2 + 64*VS_STRIDE + 64*PS_STRIDE)
#define FLASH_SMEM_BYTES (FLASH_SMEM_FLOATS * 4)

__global__ __launch_bounds__(256) void flash_attn(
    const float* __restrict__ q, const float* __restrict__ k,
    const float* __restrict__ v, float* __restrict__ o)
{
    extern __shared__ float sm[];
    float* Qs = sm;                      // [64][129]
    float* Ks = Qs + 64 * QS_STRIDE;     // [64][129]
    float* Vs = Ks + 64 * QS_STRIDE;     // [64][132]
    float* Ps = Vs + 64 * VS_STRIDE;     // [64][65]

    const int tid = threadIdx.x;
    const int tx = tid & 15;
    const int ty = tid >> 4;
    const int i0 = blockIdx.x * FBM;
    const int h  = blockIdx.y;
    const int b  = blockIdx.z;
    const int kh = h >> 2;

    const float* qbase = q + ((size_t)b * T_DIM) * QW + h * HD;
    const float* kbase = k + ((size_t)b * T_DIM) * KW + kh * HD;
    const float* vbase = v + ((size_t)b * T_DIM) * KW + kh * HD;

    const float scale = 0.08838834764831845f;

    {
        int f  = tid & 31;
        int r0 = tid >> 5;
#pragma unroll
        for (int i = 0; i < 8; i++) {
            int lr = r0 + 8 * i;
            float4 val = *(const float4*)(qbase + (size_t)(i0 + lr) * QW + 4 * f);
            float* dst = Qs + lr * QS_STRIDE + 4 * f;
            dst[0] = val.x * scale; dst[1] = val.y * scale;
            dst[2] = val.z * scale; dst[3] = val.w * scale;
        }
    }

    float m_i[4], l_i[4], O[4][8];
#pragma unroll
    for (int i = 0; i < 4; i++) {
        m_i[i] = -INFINITY;
        l_i[i] = 0.0f;
#pragma unroll
        for (int j = 0; j < 8; j++) O[i][j] = 0.0f;
    }

    const int ntiles = i0 / FBN + 1;
    for (int jt = 0; jt < ntiles; jt++) {
        const int j0 = jt * FBN;
        __syncthreads();
        {
            int f  = tid & 31;
            int r0 = tid >> 5;
#pragma unroll
            for (int i = 0; i < 8; i++) {
                int lr = r0 + 8 * i;
                float4 kv4 = *(const float4*)(kbase + (size_t)(j0 + lr) * KW + 4 * f);
                float* kd = Ks + lr * QS_STRIDE + 4 * f;
                kd[0] = kv4.x; kd[1] = kv4.y; kd[2] = kv4.z; kd[3] = kv4.w;
                float4 vv4 = *(const float4*)(vbase + (size_t)(j0 + lr) * KW + 4 * f);
                *(float4*)(Vs + lr * VS_STRIDE + 4 * f) = vv4;
            }
        }
        __syncthreads();

        float S[4][4];
#pragma unroll
        for (int i = 0; i < 4; i++)
#pragma unroll
            for (int j = 0; j < 4; j++) S[i][j] = 0.0f;

#pragma unroll 4
        for (int d = 0; d < HD; d++) {
            float a_[4], b_[4];
#pragma unroll
            for (int i = 0; i < 4; i++) a_[i] = Qs[(4 * ty + i) * QS_STRIDE + d];
#pragma unroll
            for (int j = 0; j < 4; j++) b_[j] = Ks[(4 * tx + j) * QS_STRIDE + d];
#pragma unroll
            for (int i = 0; i < 4; i++)
#pragma unroll
                for (int j = 0; j < 4; j++)
                    S[i][j] = fmaf(a_[i], b_[j], S[i][j]);
        }

        if (j0 == i0) {
#pragma unroll
            for (int i = 0; i < 4; i++)
#pragma unroll
                for (int j = 0; j < 4; j++)
                    if ((j0 + 4 * tx + j) > (i0 + 4 * ty + i)) S[i][j] = -1e30f;
        }

#pragma unroll
        for (int i = 0; i < 4; i++) {
            float rm = fmaxf(fmaxf(S[i][0], S[i][1]), fmaxf(S[i][2], S[i][3]));
#pragma unroll
            for (int off = 1; off < 16; off <<= 1)
                rm = fmaxf(rm, __shfl_xor_sync(0xffffffffu, rm, off));
            float m_new = fmaxf(m_i[i], rm);
            float alpha = __expf(m_i[i] - m_new);
            float p[4], rs = 0.0f;
#pragma unroll
            for (int j = 0; j < 4; j++) { p[j] = __expf(S[i][j] - m_new); rs += p[j]; }
#pragma unroll
            for (int off = 1; off < 16; off <<= 1)
                rs += __shfl_xor_sync(0xffffffffu, rs, off);
            l_i[i] = l_i[i] * alpha + rs;
            m_i[i] = m_new;
#pragma unroll
            for (int j = 0; j < 8; j++) O[i][j] *= alpha;
#pragma unroll
            for (int j = 0; j < 4; j++)
                Ps[(4 * ty + i) * PS_STRIDE + 4 * tx + j] = p[j];
        }
        __syncthreads();

#pragma unroll 2
        for (int s = 0; s < FBN; s++) {
            float p0 = Ps[(4 * ty + 0) * PS_STRIDE + s];
            float p1 = Ps[(4 * ty + 1) * PS_STRIDE + s];
            float p2 = Ps[(4 * ty + 2) * PS_STRIDE + s];
            float p3 = Ps[(4 * ty + 3) * PS_STRIDE + s];
            float4 v0 = *(const float4*)(Vs + s * VS_STRIDE + 8 * tx);
            float4 v1 = *(const float4*)(Vs + s * VS_STRIDE + 8 * tx + 4);
            O[0][0] = fmaf(p0, v0.x, O[0][0]); O[0][1] = fmaf(p0, v0.y, O[0][1]);
            O[0][2] = fmaf(p0, v0.z, O[0][2]); O[0][3] = fmaf(p0, v0.w, O[0][3]);
            O[0][4] = fmaf(p0, v1.x, O[0][4]); O[0][5] = fmaf(p0, v1.y, O[0][5]);
            O[0][6] = fmaf(p0, v1.z, O[0][6]); O[0][7] = fmaf(p0, v1.w, O[0][7]);
            O[1][0] = fmaf(p1, v0.x, O[1][0]); O[1][1] = fmaf(p1, v0.y, O[1][1]);
            O[1][2] = fmaf(p1, v0.z, O[1][2]); O[1][3] = fmaf(p1, v0.w, O[1][3]);
            O[1][4] = fmaf(p1, v1.x, O[1][4]); O[1][5] = fmaf(p1, v1.y, O[1][5]);
            O[1][6] = fmaf(p1, v1.z, O[1][6]); O[1][7] = fmaf(p1, v1.w, O[1][7]);
            O[2][0] = fmaf(p2, v0.x, O[2][0]); O[2][1] = fmaf(p2, v0.y, O[2][1]);
            O[2][2] = fmaf(p2, v0.z, O[2][2]); O[2][3] = fmaf(p2, v0.w, O[2][3]);
            O[2][4] = fmaf(p2, v1.x, O[2][4]); O[2][5] = fmaf(p2, v1.y, O[2][5]);
            O[2][6] = fmaf(p2, v1.z, O[2][6]); O[2][7] = fmaf(p2, v1.w, O[2][7]);
            O[3][0] = fmaf(p3, v0.x, O[3][0]); O[3][1] = fmaf(p3, v0.y, O[3][1]);
            O[3][2] = fmaf(p3, v0.z, O[3][2]); O[3][3] = fmaf(p3, v0.w, O[3][3]);
            O[3][4] = fmaf(p3, v1.x, O[3][4]); O[3][5] = fmaf(p3, v1.y, O[3][5]);
            O[3][6] = fmaf(p3, v1.z, O[3][6]); O[3][7] = fmaf(p3, v1.w, O[3][7]);
        }
    }

    float* obase = o + ((size_t)(b * T_DIM + i0)) * QW + h * HD;
#pragma unroll
    for (int i = 0; i < 4; i++) {
        float inv = 1.0f / l_i[i];
        float4 w0 = make_float4(O[i][0] * inv, O[i][1] * inv, O[i][2] * inv, O[i][3] * inv);
        float4 w1 = make_float4(O[i][4] * inv, O[i][5] * inv, O[i][6] * inv, O[i][7] * inv);
        *(float4*)(obase + (size_t)(4 * ty + i) * QW + 8 * tx)     = w0;
        *(float4*)(obase + (size_t)(4 * ty + i) * QW + 8 * tx + 4) = w1;
    }
}

// ---------------------------------------------------------------------------
extern "C" void kernel_launch(void* const* d_in, const int* in_sizes, int n_in,
                              void* d_out, int out_size)
{
    const float* x    = (const float*)d_in[0];
    const float* cosb = (const float*)d_in[1];
    const float* sinb = (const float*)d_in[2];
    const float* Wq   = (const float*)d_in[3];
    const float* Wk   = (const float*)d_in[4];
    const float* Wv   = (const float*)d_in[5];
    const float* Wo   = (const float*)d_in[6];
    float* out = (float*)d_out;

    float *qp, *kp, *vp, *ap;
    cudaGetSymbolAddress((void**)&qp, g_q);
    cudaGetSymbolAddress((void**)&kp, g_k);
    cudaGetSymbolAddress((void**)&vp, g_v);
    cudaGetSymbolAddress((void**)&ap, g_attn);

    cudaFuncSetAttribute(flash_attn, cudaFuncAttributeMaxDynamicSharedMemorySize,
                         FLASH_SMEM_BYTES);

    // Projections (tf32 tensor cores)
    gemm_tf32<<<dim3(QW / GBN, ROWS / GBM), 256>>>(x, Wq, qp, ROWS, QW, HID);
    gemm_tf32<<<dim3(KW / GBN, ROWS / GBM), 256>>>(x, Wk, kp, ROWS, KW, HID);
    gemm_tf32<<<dim3(KW / GBN, ROWS / GBM), 256>>>(x, Wv, vp, ROWS, KW, HID);

    // RoPE on q and k
    {
        int totq = ROWS * NH * (HD / 2);
        rope_kernel<<<(totq + 255) / 256, 256>>>(qp, cosb, sinb, NH);
        int totk = ROWS * NKV * (HD / 2);
        rope_kernel<<<(totk + 255) / 256, 256>>>(kp, cosb, sinb, NKV);
    }

    // Attention (fp32 flash, converted next round)
    flash_attn<<<dim3(T_DIM / FBM, NH, B_DIM), 256, FLASH_SMEM_BYTES>>>(qp, kp, vp, ap);

    // Output projection
    gemm_tf32<<<dim3(HID / GBN, ROWS / GBM), 256>>>(ap, Wo, out, ROWS, HID, HID);
}

// round 3
// speedup vs baseline: 3.0422x; 2.9653x over previous
#include <cuda_runtime.h>
#include <cuda_bf16.h>
#include <math.h>
#include <stdint.h>

#define B_DIM 2
#define T_DIM 2048
#define HID 2048
#define NH 16
#define NKV 4
#define HD 128
#define ROWS (B_DIM * T_DIM)          // 4096
#define QW (NH * HD)                  // 2048
#define KW (NKV * HD)                 // 512

// Scratch (device globals: allocation is forbidden)
__device__ float g_q[ROWS * QW];
__device__ float g_k[ROWS * KW];
__device__ float g_v[ROWS * KW];
__device__ float g_attn[ROWS * QW];

__device__ __forceinline__ float to_tf32(float x) {
    float r;
    asm("cvt.rna.tf32.f32 %0, %1;" : "=f"(r) : "f"(x));
    return r;
}
__device__ __forceinline__ uint32_t to_tf32u(float x) {
    return __float_as_uint(to_tf32(x));
}

__device__ __forceinline__ void mma_tf32(float* d, const uint32_t* a, const uint32_t* b) {
    asm volatile(
        "mma.sync.aligned.m16n8k8.row.col.f32.tf32.tf32.f32 "
        "{%0,%1,%2,%3}, {%4,%5,%6,%7}, {%8,%9}, {%0,%1,%2,%3};"
        : "+f"(d[0]), "+f"(d[1]), "+f"(d[2]), "+f"(d[3])
        : "r"(a[0]), "r"(a[1]), "r"(a[2]), "r"(a[3]), "r"(b[0]), "r"(b[1]));
}

// ---------------------------------------------------------------------------
// tf32 tensor-core GEMM: C[M,N] = A[M,K] @ B[K,N]  (unchanged from R2)
// ---------------------------------------------------------------------------
#define GBM 128
#define GBN 128
#define GBK 16
#define GST 136

__global__ __launch_bounds__(256, 2) void gemm_tf32(
    const float* __restrict__ A, const float* __restrict__ B,
    float* __restrict__ C, int M, int N, int K)
{
    __shared__ float As[GBK][GST];
    __shared__ float Bs[GBK][GST];

    const int tid  = threadIdx.x;
    const int lane = tid & 31;
    const int warp = tid >> 5;
    const int wm = (warp >> 2) * 64;
    const int wn = (warp & 3) * 32;
    const int bm = blockIdx.y * GBM;
    const int bn = blockIdx.x * GBN;

    const int am = tid >> 1;
    const int ak = (tid & 1) * 8;
    const int bk  = tid >> 4;
    const int bn8 = (tid & 15) * 8;

    const float* Ap = A + (size_t)(bm + am) * K + ak;
    const float* Bp = B + (size_t)bk * N + bn + bn8;

    float acc[4][4][4];
#pragma unroll
    for (int mi = 0; mi < 4; mi++)
#pragma unroll
        for (int ni = 0; ni < 4; ni++)
#pragma unroll
            for (int r = 0; r < 4; r++) acc[mi][ni][r] = 0.0f;

    float pa[8], pb[8];
    *(float4*)&pa[0] = *(const float4*)(Ap);
    *(float4*)&pa[4] = *(const float4*)(Ap + 4);
    *(float4*)&pb[0] = *(const float4*)(Bp);
    *(float4*)&pb[4] = *(const float4*)(Bp + 4);

    const int ntiles = K / GBK;
    for (int t = 0; t < ntiles; t++) {
#pragma unroll
        for (int i = 0; i < 8; i++) As[ak + i][am] = to_tf32(pa[i]);
#pragma unroll
        for (int i = 0; i < 8; i++) Bs[bk][bn8 + i] = to_tf32(pb[i]);
        __syncthreads();

        if (t + 1 < ntiles) {
            const float* An = Ap + (size_t)(t + 1) * GBK;
            const float* Bn = Bp + (size_t)(t + 1) * GBK * N;
            *(float4*)&pa[0] = *(const float4*)(An);
            *(float4*)&pa[4] = *(const float4*)(An + 4);
            *(float4*)&pb[0] = *(const float4*)(Bn);
            *(float4*)&pb[4] = *(const float4*)(Bn + 4);
        }

#pragma unroll
        for (int ks = 0; ks < 2; ks++) {
            const int k0 = ks * 8 + (lane & 3);
            uint32_t af[4][4], bf[4][2];
#pragma unroll
            for (int mi = 0; mi < 4; mi++) {
                const int row = wm + mi * 16 + (lane >> 2);
                af[mi][0] = __float_as_uint(As[k0][row]);
                af[mi][1] = __float_as_uint(As[k0][row + 8]);
                af[mi][2] = __float_as_uint(As[k0 + 4][row]);
                af[mi][3] = __float_as_uint(As[k0 + 4][row + 8]);
            }
#pragma unroll
            for (int ni = 0; ni < 4; ni++) {
                const int col = wn + ni * 8 + (lane >> 2);
                bf[ni][0] = __float_as_uint(Bs[k0][col]);
                bf[ni][1] = __float_as_uint(Bs[k0 + 4][col]);
            }
#pragma unroll
            for (int mi = 0; mi < 4; mi++)
#pragma unroll
                for (int ni = 0; ni < 4; ni++)
                    mma_tf32(acc[mi][ni], af[mi], bf[ni]);
        }
        __syncthreads();
    }

#pragma unroll
    for (int mi = 0; mi < 4; mi++) {
#pragma unroll
        for (int ni = 0; ni < 4; ni++) {
            const int row = bm + wm + mi * 16 + (lane >> 2);
            const int col = bn + wn + ni * 8 + (lane & 3) * 2;
            *(float2*)&C[(size_t)row * N + col] =
                make_float2(acc[mi][ni][0], acc[mi][ni][1]);
            *(float2*)&C[(size_t)(row + 8) * N + col] =
                make_float2(acc[mi][ni][2], acc[mi][ni][3]);
        }
    }
}

// ---------------------------------------------------------------------------
// RoPE in-place (unchanged)
// ---------------------------------------------------------------------------
__global__ void rope_kernel(float* __restrict__ t,
                            const float* __restrict__ cosb,
                            const float* __restrict__ sinb,
                            int heads)
{
    int idx = blockIdx.x * blockDim.x + threadIdx.x;
    int total = ROWS * heads * (HD / 2);
    if (idx >= total) return;
    int d = idx & 63;
    int h = (idx >> 6) % heads;
    int row = idx / (64 * heads);
    int tpos = row & (T_DIM - 1);

    const float c1 = cosb[tpos * HD + d];
    const float s1 = sinb[tpos * HD + d];
    const float c2 = cosb[tpos * HD + d + 64];
    const float s2 = sinb[tpos * HD + d + 64];

    float* p = t + (size_t)row * heads * HD + h * HD;
    float x1 = p[d];
    float x2 = p[d + 64];
    p[d]      = x1 * c1 - x2 * s1;
    p[d + 64] = x2 * c2 + x1 * s2;
}

// ---------------------------------------------------------------------------
// tf32 tensor-core flash attention, causal, GQA.
// BM=128 (8 warps x m16), BN=64 kv tile. Q in registers, K/V/P in smem.
// ---------------------------------------------------------------------------
#define FBM 128
#define FBN 64
#define KS_ST 132   // bank = 4*row + k  -> conflict-free for K B-frags
#define VS_ST 136   // bank = 8*k + n    -> conflict-free for V B-frags
#define PS_ST 68    // bank = 4*row + k  -> conflict-free for P A-frags
#define FL_SMEM_FLOATS (64*KS_ST + 64*VS_ST + 128*PS_ST)
#define FL_SMEM_BYTES (FL_SMEM_FLOATS * 4)

__global__ __launch_bounds__(256) void flash_tf32(
    const float* __restrict__ q, const float* __restrict__ k,
    const float* __restrict__ v, float* __restrict__ o)
{
    extern __shared__ float sm[];
    float* Ks = sm;                 // [64][132]  row=kv, col=d
    float* Vs = Ks + 64 * KS_ST;    // [64][136]  row=kv, col=d
    float* Ps = Vs + 64 * VS_ST;    // [128][68]  row=m,  col=kv

    const int tid  = threadIdx.x;
    const int lane = tid & 31;
    const int warp = tid >> 5;
    const int g = lane >> 2;        // 0..7
    const int t = lane & 3;         // 0..3
    const int wm = warp * 16;
    const int i0 = (gridDim.x - 1 - (int)blockIdx.x) * FBM;  // heavy CTAs first
    const int h  = blockIdx.y;
    const int b  = blockIdx.z;
    const int kh = h >> 2;

    const float* qbase = q + ((size_t)b * T_DIM + i0) * QW + h * HD;
    const float* kbase = k + ((size_t)b * T_DIM) * KW + kh * HD;
    const float* vbase = v + ((size_t)b * T_DIM) * KW + kh * HD;

    const float scale = 0.08838834764831845f;   // 1/sqrt(128)

    // Q fragments: qf[kc][.] covers k-slice [8kc, 8kc+8) of this warp's 16 rows
    uint32_t qf[16][4];
    {
        const float* q0 = qbase + (size_t)(wm + g) * QW;
        const float* q8 = qbase + (size_t)(wm + g + 8) * QW;
#pragma unroll
        for (int kc = 0; kc < 16; kc++) {
            int c = kc * 8 + t;
            qf[kc][0] = to_tf32u(q0[c] * scale);
            qf[kc][1] = to_tf32u(q8[c] * scale);
            qf[kc][2] = to_tf32u(q0[c + 4] * scale);
            qf[kc][3] = to_tf32u(q8[c + 4] * scale);
        }
    }

    float O[16][4];
#pragma unroll
    for (int ni = 0; ni < 16; ni++)
#pragma unroll
        for (int r = 0; r < 4; r++) O[ni][r] = 0.0f;
    float m0 = -INFINITY, m1 = -INFINITY, l0 = 0.0f, l1 = 0.0f;

    const int row0 = i0 + wm + g;
    const int row1 = row0 + 8;

    const int ntiles = i0 / FBN + 2;
    for (int jt = 0; jt < ntiles; jt++) {
        const int j0 = jt * FBN;
        __syncthreads();   // protect prior-iteration Vs/Ps reads

        // Load K/V tile: 64 rows x 128 d. Thread covers rows (tid>>5)+8i, quad 4*(tid&31).
        {
            const int f  = tid & 31;
            const int r0 = tid >> 5;
#pragma unroll
            for (int i = 0; i < 8; i++) {
                const int r = r0 + 8 * i;
                float4 kv4 = *(const float4*)(kbase + (size_t)(j0 + r) * KW + 4 * f);
                *(float4*)(Ks + r * KS_ST + 4 * f) =
                    make_float4(to_tf32(kv4.x), to_tf32(kv4.y), to_tf32(kv4.z), to_tf32(kv4.w));
                float4 vv4 = *(const float4*)(vbase + (size_t)(j0 + r) * KW + 4 * f);
                *(float4*)(Vs + r * VS_ST + 4 * f) =
                    make_float4(to_tf32(vv4.x), to_tf32(vv4.y), to_tf32(vv4.z), to_tf32(vv4.w));
            }
        }
        __syncthreads();

        // S = Q @ K^T : 8 n-tiles of n8, 16 k-steps
        float S[8][4];
#pragma unroll
        for (int ni = 0; ni < 8; ni++)
#pragma unroll
            for (int r = 0; r < 4; r++) S[ni][r] = 0.0f;

#pragma unroll
        for (int kc = 0; kc < 16; kc++) {
#pragma unroll
            for (int ni = 0; ni < 8; ni++) {
                uint32_t bf[2];
                const float* kp = Ks + (ni * 8 + g) * KS_ST + kc * 8 + t;
                bf[0] = __float_as_uint(kp[0]);
                bf[1] = __float_as_uint(kp[4]);
                mma_tf32(S[ni], qf[kc], bf);
            }
        }

        // causal mask (only tiles overlapping the diagonal)
        if (j0 + FBN > i0) {
#pragma unroll
            for (int ni = 0; ni < 8; ni++) {
                const int col = j0 + ni * 8 + 2 * t;
                if (col     > row0) S[ni][0] = -1e30f;
                if (col + 1 > row0) S[ni][1] = -1e30f;
                if (col     > row1) S[ni][2] = -1e30f;
                if (col + 1 > row1) S[ni][3] = -1e30f;
            }
        }

        // online softmax (rows row0, row1 owned by 4 lanes each)
        float rm0 = -INFINITY, rm1 = -INFINITY;
#pragma unroll
        for (int ni = 0; ni < 8; ni++) {
            rm0 = fmaxf(rm0, fmaxf(S[ni][0], S[ni][1]));
            rm1 = fmaxf(rm1, fmaxf(S[ni][2], S[ni][3]));
        }
        rm0 = fmaxf(rm0, __shfl_xor_sync(0xffffffffu, rm0, 1));
        rm0 = fmaxf(rm0, __shfl_xor_sync(0xffffffffu, rm0, 2));
        rm1 = fmaxf(rm1, __shfl_xor_sync(0xffffffffu, rm1, 1));
        rm1 = fmaxf(rm1, __shfl_xor_sync(0xffffffffu, rm1, 2));

        const float mn0 = fmaxf(m0, rm0);
        const float mn1 = fmaxf(m1, rm1);
        const float a0 = __expf(m0 - mn0);
        const float a1 = __expf(m1 - mn1);
        m0 = mn0; m1 = mn1;

        float rs0 = 0.0f, rs1 = 0.0f;
#pragma unroll
        for (int ni = 0; ni < 8; ni++) {
            S[ni][0] = __expf(S[ni][0] - mn0);
            S[ni][1] = __expf(S[ni][1] - mn0);
            S[ni][2] = __expf(S[ni][2] - mn1);
            S[ni][3] = __expf(S[ni][3] - mn1);
            rs0 += S[ni][0] + S[ni][1];
            rs1 += S[ni][2] + S[ni][3];
        }
        rs0 += __shfl_xor_sync(0xffffffffu, rs0, 1);
        rs0 += __shfl_xor_sync(0xffffffffu, rs0, 2);
        rs1 += __shfl_xor_sync(0xffffffffu, rs1, 1);
        rs1 += __shfl_xor_sync(0xffffffffu, rs1, 2);
        l0 = l0 * a0 + rs0;
        l1 = l1 * a1 + rs1;

#pragma unroll
        for (int ni = 0; ni < 16; ni++) {
            O[ni][0] *= a0; O[ni][1] *= a0;
            O[ni][2] *= a1; O[ni][3] *= a1;
        }

        // store P (as tf32) for re-fragmentation
#pragma unroll
        for (int ni = 0; ni < 8; ni++) {
            *(float2*)(Ps + (wm + g) * PS_ST + ni * 8 + 2 * t) =
                make_float2(to_tf32(S[ni][0]), to_tf32(S[ni][1]));
            *(float2*)(Ps + (wm + g + 8) * PS_ST + ni * 8 + 2 * t) =
                make_float2(to_tf32(S[ni][2]), to_tf32(S[ni][3]));
        }
        __syncthreads();

        // O += P @ V : k-dim = 64 kv (8 chunks), n-dim = 128 d (16 tiles)
#pragma unroll
        for (int kc = 0; kc < 8; kc++) {
            uint32_t pa[4];
            const float* pp0 = Ps + (wm + g) * PS_ST + kc * 8 + t;
            const float* pp8 = Ps + (wm + g + 8) * PS_ST + kc * 8 + t;
            pa[0] = __float_as_uint(pp0[0]);
            pa[1] = __float_as_uint(pp8[0]);
            pa[2] = __float_as_uint(pp0[4]);
            pa[3] = __float_as_uint(pp8[4]);
#pragma unroll
            for (int ni = 0; ni < 16; ni++) {
                uint32_t bf[2];
                const float* vp = Vs + (kc * 8 + t) * VS_ST + ni * 8 + g;
                bf[0] = __float_as_uint(vp[0]);
                bf[1] = __float_as_uint(vp[4 * VS_ST]);
                mma_tf32(O[ni], pa, bf);
            }
        }
    }

    // epilogue
    const float il0 = 1.0f / l0;
    const float il1 = 1.0f / l1;
    float* ob = o + ((size_t)b * T_DIM + i0) * QW + h * HD;
#pragma unroll
    for (int ni = 0; ni < 16; ni++) {
        *(float2*)(ob + (size_t)(wm + g) * QW + ni * 8 + 2 * t) =
            make_float2(O[ni][0] * il0, O[ni][1] * il0);
        *(float2*)(ob + (size_t)(wm + g + 8) * QW + ni * 8 + 2 * t) =
            make_float2(O[ni][2] * il1, O[ni][3] * il1);
    }
}

// ---------------------------------------------------------------------------
extern "C" void kernel_launch(void* const* d_in, const int* in_sizes, int n_in,
                              void* d_out, int out_size)
{
    const float* x    = (const float*)d_in[0];
    const float* cosb = (const float*)d_in[1];
    const float* sinb = (const float*)d_in[2];
    const float* Wq   = (const float*)d_in[3];
    const float* Wk   = (const float*)d_in[4];
    const float* Wv   = (const float*)d_in[5];
    const float* Wo   = (const float*)d_in[6];
    float* out = (float*)d_out;

    float *qp, *kp, *vp, *ap;
    cudaGetSymbolAddress((void**)&qp, g_q);
    cudaGetSymbolAddress((void**)&kp, g_k);
    cudaGetSymbolAddress((void**)&vp, g_v);
    cudaGetSymbolAddress((void**)&ap, g_attn);

    cudaFuncSetAttribute(flash_tf32, cudaFuncAttributeMaxDynamicSharedMemorySize,
                         FL_SMEM_BYTES);

    // Projections (tf32 tensor cores)
    gemm_tf32<<<dim3(QW / GBN, ROWS / GBM), 256>>>(x, Wq, qp, ROWS, QW, HID);
    gemm_tf32<<<dim3(KW / GBN, ROWS / GBM), 256>>>(x, Wk, kp, ROWS, KW, HID);
    gemm_tf32<<<dim3(KW / GBN, ROWS / GBM), 256>>>(x, Wv, vp, ROWS, KW, HID);

    // RoPE on q and k
    {
        int totq = ROWS * NH * (HD / 2);
        rope_kernel<<<(totq + 255) / 256, 256>>>(qp, cosb, sinb, NH);
        int totk = ROWS * NKV * (HD / 2);
        rope_kernel<<<(totk + 255) / 256, 256>>>(kp, cosb, sinb, NKV);
    }

    // Attention (tf32 tensor cores)
    flash_tf32<<<dim3(T_DIM / FBM, NH, B_DIM), 256, FL_SMEM_BYTES>>>(qp, kp, vp, ap);

    // Output projection
    gemm_tf32<<<dim3(HID / GBN, ROWS / GBM), 256>>>(ap, Wo, out, ROWS, HID, HID);
}

// round 4
// speedup vs baseline: 3.9490x; 1.2981x over previous
#include <cuda_runtime.h>
#include <cuda_bf16.h>
#include <math.h>
#include <stdint.h>

#define B_DIM 2
#define T_DIM 2048
#define HID 2048
#define NH 16
#define NKV 4
#define HD 128
#define ROWS (B_DIM * T_DIM)          // 4096
#define QW (NH * HD)                  // 2048
#define KW (NKV * HD)                 // 512

// Scratch (device globals: allocation is forbidden)
__device__ float g_q[ROWS * QW];
__device__ float g_k[ROWS * KW];
__device__ float g_v[ROWS * KW];
__device__ float g_attn[ROWS * QW];

__device__ __forceinline__ float to_tf32(float x) {
    float r;
    asm("cvt.rna.tf32.f32 %0, %1;" : "=f"(r) : "f"(x));
    return r;
}
__device__ __forceinline__ uint32_t cvt_u(float x) {
    return __float_as_uint(to_tf32(x));
}

__device__ __forceinline__ void mma_tf32(float* d, const uint32_t* a, const uint32_t* b) {
    asm volatile(
        "mma.sync.aligned.m16n8k8.row.col.f32.tf32.tf32.f32 "
        "{%0,%1,%2,%3}, {%4,%5,%6,%7}, {%8,%9}, {%0,%1,%2,%3};"
        : "+f"(d[0]), "+f"(d[1]), "+f"(d[2]), "+f"(d[3])
        : "r"(a[0]), "r"(a[1]), "r"(a[2]), "r"(a[3]), "r"(b[0]), "r"(b[1]));
}

__device__ __forceinline__ void cp16(void* dst, const void* src) {
    uint32_t d = (uint32_t)__cvta_generic_to_shared(dst);
    asm volatile("cp.async.ca.shared.global [%0], [%1], 16;" :: "r"(d), "l"(src));
}
__device__ __forceinline__ void cp_commit() { asm volatile("cp.async.commit_group;" ::); }
template<int N> __device__ __forceinline__ void cp_wait() {
    asm volatile("cp.async.wait_group %0;" :: "n"(N));
}

// ---------------------------------------------------------------------------
// tf32 GEMM core: C[128 rows @bm][128 cols @bn] += A[*,2048] @ B[2048,ld]
// 3-stage cp.async pipeline. As[m][k] stride 20, Bs[k][n] stride 136.
// ---------------------------------------------------------------------------
#define AST 20
#define BST 136
#define A_STG (128 * AST)   // 2560 floats
#define B_STG (16 * BST)    // 2176 floats
#define GEMM_SMEM ((3 * A_STG + 3 * B_STG) * 4)

__device__ __forceinline__ void gemm_core(
    const float* __restrict__ A, const float* __restrict__ B,
    float* __restrict__ C, int ld, int bm, int bn, bool round_out, float* sm)
{
    float* As = sm;
    float* Bs = sm + 3 * A_STG;
    const int tid = threadIdx.x, lane = tid & 31, warp = tid >> 5;
    const int g = lane >> 2, t = lane & 3;
    const int wm = (warp >> 2) * 64, wn = (warp & 3) * 32;

    const int ar0 = tid >> 2, akc = (tid & 3) * 4;
    const int br0 = tid >> 5, bnc = (tid & 31) * 4;
    const float* Ab = A + (size_t)(bm + ar0) * HID + akc;
    const float* Bb = B + (size_t)br0 * ld + bn + bnc;

    float acc[4][4][4];
#pragma unroll
    for (int mi = 0; mi < 4; mi++)
#pragma unroll
        for (int ni = 0; ni < 4; ni++)
#pragma unroll
            for (int r = 0; r < 4; r++) acc[mi][ni][r] = 0.0f;

#define LOAD_STAGE(st, k0) { \
    float* Ad = As + (st) * A_STG; float* Bd = Bs + (st) * B_STG; \
    const float* Ap = Ab + (k0); \
    cp16(Ad + ar0 * AST + akc, Ap); \
    cp16(Ad + (ar0 + 64) * AST + akc, Ap + (size_t)64 * HID); \
    const float* Bp = Bb + (size_t)(k0) * ld; \
    cp16(Bd + br0 * BST + bnc, Bp); \
    cp16(Bd + (br0 + 8) * BST + bnc, Bp + (size_t)8 * ld); \
    cp_commit(); }

    LOAD_STAGE(0, 0)
    LOAD_STAGE(1, 16)

    const int NT = HID / 16;   // 128 K-tiles
    for (int tt = 0; tt < NT; tt++) {
        cp_wait<1>();
        __syncthreads();
        if (tt + 2 < NT) LOAD_STAGE((tt + 2) % 3, (tt + 2) * 16)

        const float* Ast = As + (tt % 3) * A_STG;
        const float* Bst = Bs + (tt % 3) * B_STG;
#pragma unroll
        for (int ks = 0; ks < 2; ks++) {
            const int kk = ks * 8 + t;
            uint32_t af[4][4], bf[4][2];
#pragma unroll
            for (int mi = 0; mi < 4; mi++) {
                const float* ap = Ast + (wm + mi * 16 + g) * AST + kk;
                af[mi][0] = cvt_u(ap[0]);
                af[mi][1] = cvt_u(ap[8 * AST]);
                af[mi][2] = cvt_u(ap[4]);
                af[mi][3] = cvt_u(ap[8 * AST + 4]);
            }
#pragma unroll
            for (int ni = 0; ni < 4; ni++) {
                const float* bp = Bst + kk * BST + wn + ni * 8 + g;
                bf[ni][0] = cvt_u(bp[0]);
                bf[ni][1] = cvt_u(bp[4 * BST]);
            }
#pragma unroll
            for (int mi = 0; mi < 4; mi++)
#pragma unroll
                for (int ni = 0; ni < 4; ni++)
                    mma_tf32(acc[mi][ni], af[mi], bf[ni]);
        }
    }
#undef LOAD_STAGE

#pragma unroll
    for (int mi = 0; mi < 4; mi++) {
#pragma unroll
        for (int ni = 0; ni < 4; ni++) {
            const int row = bm + wm + mi * 16 + g;
            const int col = bn + wn + ni * 8 + 2 * t;
            float v0 = acc[mi][ni][0], v1 = acc[mi][ni][1];
            float v2 = acc[mi][ni][2], v3 = acc[mi][ni][3];
            if (round_out) {
                v0 = to_tf32(v0); v1 = to_tf32(v1);
                v2 = to_tf32(v2); v3 = to_tf32(v3);
            }
            *(float2*)&C[(size_t)row * ld + col] = make_float2(v0, v1);
            *(float2*)&C[(size_t)(row + 8) * ld + col] = make_float2(v2, v3);
        }
    }
}

// Fused QKV projection: grid.x routes to Wq (0..15), Wk (16..19), Wv (20..23).
__global__ __launch_bounds__(256, 2) void gemm_qkv(
    const float* __restrict__ x,
    const float* __restrict__ Wq, const float* __restrict__ Wk, const float* __restrict__ Wv,
    float* __restrict__ qp, float* __restrict__ kp, float* __restrict__ vp)
{
    extern __shared__ float sm[];
    const int bx = blockIdx.x;
    const float* B; float* C; int ld; int bn; bool rnd = false;
    if (bx < 16)      { B = Wq; C = qp; ld = QW; bn = bx * 128; }
    else if (bx < 20) { B = Wk; C = kp; ld = KW; bn = (bx - 16) * 128; }
    else              { B = Wv; C = vp; ld = KW; bn = (bx - 20) * 128; rnd = true; }
    gemm_core(x, B, C, ld, blockIdx.y * 128, bn, rnd, sm);
}

__global__ __launch_bounds__(256, 2) void gemm_wo(
    const float* __restrict__ A, const float* __restrict__ W, float* __restrict__ C)
{
    extern __shared__ float sm[];
    gemm_core(A, W, C, HID, blockIdx.y * 128, blockIdx.x * 128, false, sm);
}

// ---------------------------------------------------------------------------
// RoPE in-place, outputs rounded to tf32 (consumed by flash without cvt).
// ---------------------------------------------------------------------------
__global__ void rope_kernel(float* __restrict__ t,
                            const float* __restrict__ cosb,
                            const float* __restrict__ sinb,
                            int heads)
{
    int idx = blockIdx.x * blockDim.x + threadIdx.x;
    int total = ROWS * heads * (HD / 2);
    if (idx >= total) return;
    int d = idx & 63;
    int h = (idx >> 6) % heads;
    int row = idx / (64 * heads);
    int tpos = row & (T_DIM - 1);

    const float c1 = cosb[tpos * HD + d];
    const float s1 = sinb[tpos * HD + d];
    const float c2 = cosb[tpos * HD + d + 64];
    const float s2 = sinb[tpos * HD + d + 64];

    float* p = t + (size_t)row * heads * HD + h * HD;
    float x1 = p[d];
    float x2 = p[d + 64];
    p[d]      = to_tf32(x1 * c1 - x2 * s1);
    p[d + 64] = to_tf32(x2 * c2 + x1 * s2);
}

// ---------------------------------------------------------------------------
// tf32 flash attention with cp.async double-buffered K/V.
// BM=128 (8 warps x m16), BN=64. Inputs q/k/v pre-rounded to tf32.
// ---------------------------------------------------------------------------
#define FBM 128
#define FBN 64
#define KS_ST 132
#define VS_ST 136
#define PS_ST 68
#define K_STG (64 * KS_ST)
#define V_STG (64 * VS_ST)
#define FL_SMEM ((2 * K_STG + 2 * V_STG + 128 * PS_ST) * 4)   // 172032 B

__global__ __launch_bounds__(256, 1) void flash_tf32(
    const float* __restrict__ q, const float* __restrict__ k,
    const float* __restrict__ v, float* __restrict__ o)
{
    extern __shared__ float sm[];
    float* Ks = sm;                      // [2][64][132]
    float* Vs = Ks + 2 * K_STG;          // [2][64][136]
    float* Ps = Vs + 2 * V_STG;          // [128][68]

    const int tid  = threadIdx.x;
    const int lane = tid & 31;
    const int warp = tid >> 5;
    const int g = lane >> 2;
    const int t = lane & 3;
    const int wm = warp * 16;
    const int i0 = (gridDim.x - 1 - (int)blockIdx.x) * FBM;  // heavy CTAs first
    const int h  = blockIdx.y;
    const int b  = blockIdx.z;
    const int kh = h >> 2;

    const float* qbase = q + ((size_t)b * T_DIM + i0) * QW + h * HD;
    const float* kbase = k + ((size_t)b * T_DIM) * KW + kh * HD;
    const float* vbase = v + ((size_t)b * T_DIM) * KW + kh * HD;

    const float scale = 0.08838834764831845f;   // 1/sqrt(128), applied to S

    // Q fragments (already tf32-rounded; no scale here)
    uint32_t qf[16][4];
    {
        const float* q0 = qbase + (size_t)(wm + g) * QW;
        const float* q8 = qbase + (size_t)(wm + g + 8) * QW;
#pragma unroll
        for (int kc = 0; kc < 16; kc++) {
            int c = kc * 8 + t;
            qf[kc][0] = __float_as_uint(q0[c]);
            qf[kc][1] = __float_as_uint(q8[c]);
            qf[kc][2] = __float_as_uint(q0[c + 4]);
            qf[kc][3] = __float_as_uint(q8[c + 4]);
        }
    }

    float O[16][4];
#pragma unroll
    for (int ni = 0; ni < 16; ni++)
#pragma unroll
        for (int r = 0; r < 4; r++) O[ni][r] = 0.0f;
    float m0 = -INFINITY, m1 = -INFINITY, l0 = 0.0f, l1 = 0.0f;

    const int row0 = i0 + wm + g;
    const int row1 = row0 + 8;
    const int l4 = lane * 4;

#define LOAD_KV(st, j0) { \
    float* Kd = Ks + (st) * K_STG; float* Vd = Vs + (st) * V_STG; \
    _Pragma("unroll") \
    for (int i = 0; i < 8; i++) { \
        const int r = warp + 8 * i; \
        cp16(Kd + r * KS_ST + l4, kbase + (size_t)((j0) + r) * KW + l4); \
        cp16(Vd + r * VS_ST + l4, vbase + (size_t)((j0) + r) * KW + l4); \
    } \
    cp_commit(); }

    const int ntiles = i0 / FBN + 2;
    LOAD_KV(0, 0)

    for (int jt = 0; jt < ntiles; jt++) {
        const int j0 = jt * FBN;
        cp_wait<0>();
        __syncthreads();
        if (jt + 1 < ntiles) LOAD_KV((jt + 1) & 1, j0 + FBN)

        const float* Kst = Ks + (jt & 1) * K_STG;
        const float* Vst = Vs + (jt & 1) * V_STG;

        // S = Q @ K^T
        float S[8][4];
#pragma unroll
        for (int ni = 0; ni < 8; ni++)
#pragma unroll
            for (int r = 0; r < 4; r++) S[ni][r] = 0.0f;

#pragma unroll
        for (int kc = 0; kc < 16; kc++) {
#pragma unroll
            for (int ni = 0; ni < 8; ni++) {
                uint32_t bf[2];
                const float* kp = Kst + (ni * 8 + g) * KS_ST + kc * 8 + t;
                bf[0] = __float_as_uint(kp[0]);
                bf[1] = __float_as_uint(kp[4]);
                mma_tf32(S[ni], qf[kc], bf);
            }
        }

        // scale then causal mask
#pragma unroll
        for (int ni = 0; ni < 8; ni++)
#pragma unroll
            for (int r = 0; r < 4; r++) S[ni][r] *= scale;

        if (j0 + FBN > i0) {
#pragma unroll
            for (int ni = 0; ni < 8; ni++) {
                const int col = j0 + ni * 8 + 2 * t;
                if (col     > row0) S[ni][0] = -1e30f;
                if (col + 1 > row0) S[ni][1] = -1e30f;
                if (col     > row1) S[ni][2] = -1e30f;
                if (col + 1 > row1) S[ni][3] = -1e30f;
            }
        }

        // online softmax
        float rm0 = -INFINITY, rm1 = -INFINITY;
#pragma unroll
        for (int ni = 0; ni < 8; ni++) {
            rm0 = fmaxf(rm0, fmaxf(S[ni][0], S[ni][1]));
            rm1 = fmaxf(rm1, fmaxf(S[ni][2], S[ni][3]));
        }
        rm0 = fmaxf(rm0, __shfl_xor_sync(0xffffffffu, rm0, 1));
        rm0 = fmaxf(rm0, __shfl_xor_sync(0xffffffffu, rm0, 2));
        rm1 = fmaxf(rm1, __shfl_xor_sync(0xffffffffu, rm1, 1));
        rm1 = fmaxf(rm1, __shfl_xor_sync(0xffffffffu, rm1, 2));

        const float mn0 = fmaxf(m0, rm0);
        const float mn1 = fmaxf(m1, rm1);
        const float a0 = __expf(m0 - mn0);
        const float a1 = __expf(m1 - mn1);
        m0 = mn0; m1 = mn1;

        float rs0 = 0.0f, rs1 = 0.0f;
#pragma unroll
        for (int ni = 0; ni < 8; ni++) {
            S[ni][0] = __expf(S[ni][0] - mn0);
            S[ni][1] = __expf(S[ni][1] - mn0);
            S[ni][2] = __expf(S[ni][2] - mn1);
            S[ni][3] = __expf(S[ni][3] - mn1);
            rs0 += S[ni][0] + S[ni][1];
            rs1 += S[ni][2] + S[ni][3];
        }
        rs0 += __shfl_xor_sync(0xffffffffu, rs0, 1);
        rs0 += __shfl_xor_sync(0xffffffffu, rs0, 2);
        rs1 += __shfl_xor_sync(0xffffffffu, rs1, 1);
        rs1 += __shfl_xor_sync(0xffffffffu, rs1, 2);
        l0 = l0 * a0 + rs0;
        l1 = l1 * a1 + rs1;

#pragma unroll
        for (int ni = 0; ni < 16; ni++) {
            O[ni][0] *= a0; O[ni][1] *= a0;
            O[ni][2] *= a1; O[ni][3] *= a1;
        }

        // store P (tf32-rounded) for re-fragmentation
#pragma unroll
        for (int ni = 0; ni < 8; ni++) {
            *(float2*)(Ps + (wm + g) * PS_ST + ni * 8 + 2 * t) =
                make_float2(to_tf32(S[ni][0]), to_tf32(S[ni][1]));
            *(float2*)(Ps + (wm + g + 8) * PS_ST + ni * 8 + 2 * t) =
                make_float2(to_tf32(S[ni][2]), to_tf32(S[ni][3]));
        }
        __syncthreads();

        // O += P @ V
#pragma unroll
        for (int kc = 0; kc < 8; kc++) {
            uint32_t pa[4];
            const float* pp0 = Ps + (wm + g) * PS_ST + kc * 8 + t;
            const float* pp8 = Ps + (wm + g + 8) * PS_ST + kc * 8 + t;
            pa[0] = __float_as_uint(pp0[0]);
            pa[1] = __float_as_uint(pp8[0]);
            pa[2] = __float_as_uint(pp0[4]);
            pa[3] = __float_as_uint(pp8[4]);
#pragma unroll
            for (int ni = 0; ni < 16; ni++) {
                uint32_t bf[2];
                const float* vp = Vst + (kc * 8 + t) * VS_ST + ni * 8 + g;
                bf[0] = __float_as_uint(vp[0]);
                bf[1] = __float_as_uint(vp[4 * VS_ST]);
                mma_tf32(O[ni], pa, bf);
            }
        }
    }
#undef LOAD_KV

    // epilogue
    const float il0 = 1.0f / l0;
    const float il1 = 1.0f / l1;
    float* ob = o + ((size_t)b * T_DIM + i0) * QW + h * HD;
#pragma unroll
    for (int ni = 0; ni < 16; ni++) {
        *(float2*)(ob + (size_t)(wm + g) * QW + ni * 8 + 2 * t) =
            make_float2(O[ni][0] * il0, O[ni][1] * il0);
        *(float2*)(ob + (size_t)(wm + g + 8) * QW + ni * 8 + 2 * t) =
            make_float2(O[ni][2] * il1, O[ni][3] * il1);
    }
}

// ---------------------------------------------------------------------------
extern "C" void kernel_launch(void* const* d_in, const int* in_sizes, int n_in,
                              void* d_out, int out_size)
{
    const float* x    = (const float*)d_in[0];
    const float* cosb = (const float*)d_in[1];
    const float* sinb = (const float*)d_in[2];
    const float* Wq   = (const float*)d_in[3];
    const float* Wk   = (const float*)d_in[4];
    const float* Wv   = (const float*)d_in[5];
    const float* Wo   = (const float*)d_in[6];
    float* out = (float*)d_out;

    float *qp, *kp, *vp, *ap;
    cudaGetSymbolAddress((void**)&qp, g_q);
    cudaGetSymbolAddress((void**)&kp, g_k);
    cudaGetSymbolAddress((void**)&vp, g_v);
    cudaGetSymbolAddress((void**)&ap, g_attn);

    cudaFuncSetAttribute(gemm_qkv, cudaFuncAttributeMaxDynamicSharedMemorySize, GEMM_SMEM);
    cudaFuncSetAttribute(gemm_wo, cudaFuncAttributeMaxDynamicSharedMemorySize, GEMM_SMEM);
    cudaFuncSetAttribute(flash_tf32, cudaFuncAttributeMaxDynamicSharedMemorySize, FL_SMEM);

    // Fused QKV projections
    gemm_qkv<<<dim3(24, ROWS / 128), 256, GEMM_SMEM>>>(x, Wq, Wk, Wv, qp, kp, vp);

    // RoPE on q and k (rounds outputs to tf32)
    {
        int totq = ROWS * NH * (HD / 2);
        rope_kernel<<<(totq + 255) / 256, 256>>>(qp, cosb, sinb, NH);
        int totk = ROWS * NKV * (HD / 2);
        rope_kernel<<<(totk + 255) / 256, 256>>>(kp, cosb, sinb, NKV);
    }

    // Attention
    flash_tf32<<<dim3(T_DIM / FBM, NH, B_DIM), 256, FL_SMEM>>>(qp, kp, vp, ap);

    // Output projection
    gemm_wo<<<dim3(HID / 128, ROWS / 128), 256, GEMM_SMEM>>>(ap, Wo, out);
}

// round 5
// speedup vs baseline: 3.9781x; 1.0074x over previous
#include <cuda_runtime.h>
#include <cuda_bf16.h>
#include <math.h>
#include <stdint.h>

#define B_DIM 2
#define T_DIM 2048
#define HID 2048
#define NH 16
#define NKV 4
#define HD 128
#define ROWS (B_DIM * T_DIM)          // 4096
#define QW (NH * HD)                  // 2048
#define KW (NKV * HD)                 // 512

// Scratch (device globals: allocation is forbidden)
__device__ float g_q[ROWS * QW];
__device__ float g_k[ROWS * KW];
__device__ float g_v[ROWS * KW];
__device__ float g_attn[ROWS * QW];
// tf32-pre-rounded operand copies
__device__ float g_xr[ROWS * HID];
__device__ float g_wq[HID * QW];
__device__ float g_wk[HID * KW];
__device__ float g_wv[HID * KW];
__device__ float g_wo[QW * HID];

__device__ __forceinline__ float to_tf32(float x) {
    float r;
    asm("cvt.rna.tf32.f32 %0, %1;" : "=f"(r) : "f"(x));
    return r;
}

__device__ __forceinline__ void mma_tf32(float* d, const uint32_t* a, const uint32_t* b) {
    asm volatile(
        "mma.sync.aligned.m16n8k8.row.col.f32.tf32.tf32.f32 "
        "{%0,%1,%2,%3}, {%4,%5,%6,%7}, {%8,%9}, {%0,%1,%2,%3};"
        : "+f"(d[0]), "+f"(d[1]), "+f"(d[2]), "+f"(d[3])
        : "r"(a[0]), "r"(a[1]), "r"(a[2]), "r"(a[3]), "r"(b[0]), "r"(b[1]));
}

__device__ __forceinline__ void cp16(void* dst, const void* src) {
    uint32_t d = (uint32_t)__cvta_generic_to_shared(dst);
    asm volatile("cp.async.ca.shared.global [%0], [%1], 16;" :: "r"(d), "l"(src));
}
__device__ __forceinline__ void cp_commit() { asm volatile("cp.async.commit_group;" ::); }
template<int N> __device__ __forceinline__ void cp_wait() {
    asm volatile("cp.async.wait_group %0;" :: "n"(N));
}

// ---------------------------------------------------------------------------
// Pre-round arrays to tf32 (idempotent; graph-replay safe).
// ---------------------------------------------------------------------------
__global__ void round_tf32_kernel(const float* __restrict__ in,
                                  float* __restrict__ out, int n4)
{
    int i = blockIdx.x * blockDim.x + threadIdx.x;
    if (i < n4) {
        float4 v = ((const float4*)in)[i];
        ((float4*)out)[i] = make_float4(to_tf32(v.x), to_tf32(v.y),
                                        to_tf32(v.z), to_tf32(v.w));
    }
}

// ---------------------------------------------------------------------------
// tf32 GEMM core: C[128 @bm][256 @bn] = A[*,2048] @ B[2048,ld]
// Inputs pre-rounded to tf32 (no cvt in loop). 8 warps (2x4), warp 64x64.
// 3-stage cp.async pipeline. As[m][k] stride 20, Bs[k][n] stride 264.
// ---------------------------------------------------------------------------
#define AST 20
#define BST 264
#define A_STG (128 * AST)   // 2560 floats
#define B_STG (16 * BST)    // 4224 floats
#define GEMM_SMEM ((3 * A_STG + 3 * B_STG) * 4)   // 81408 B

__device__ __forceinline__ void gemm_core(
    const float* __restrict__ A, const float* __restrict__ B,
    float* __restrict__ C, int ld, int bm, int bn, bool round_out, float* sm)
{
    float* As = sm;
    float* Bs = sm + 3 * A_STG;
    const int tid = threadIdx.x, lane = tid & 31, warp = tid >> 5;
    const int g = lane >> 2, t = lane & 3;
    const int wm = (warp >> 2) * 64, wn = (warp & 3) * 64;

    const int ar0 = tid >> 2, akc = (tid & 3) * 4;
    const int br0 = tid >> 6, bnc = (tid & 63) * 4;
    const float* Ab = A + (size_t)(bm + ar0) * HID + akc;
    const float* Bb = B + (size_t)br0 * ld + bn + bnc;

    float acc[4][8][4];
#pragma unroll
    for (int mi = 0; mi < 4; mi++)
#pragma unroll
        for (int ni = 0; ni < 8; ni++)
#pragma unroll
            for (int r = 0; r < 4; r++) acc[mi][ni][r] = 0.0f;

#define LOAD_STAGE(st, k0) { \
    float* Ad = As + (st) * A_STG; float* Bd = Bs + (st) * B_STG; \
    const float* Ap = Ab + (k0); \
    cp16(Ad + ar0 * AST + akc, Ap); \
    cp16(Ad + (ar0 + 64) * AST + akc, Ap + (size_t)64 * HID); \
    const float* Bp = Bb + (size_t)(k0) * ld; \
    cp16(Bd + br0 * BST + bnc, Bp); \
    cp16(Bd + (br0 + 4) * BST + bnc, Bp + (size_t)4 * ld); \
    cp16(Bd + (br0 + 8) * BST + bnc, Bp + (size_t)8 * ld); \
    cp16(Bd + (br0 + 12) * BST + bnc, Bp + (size_t)12 * ld); \
    cp_commit(); }

    LOAD_STAGE(0, 0)
    LOAD_STAGE(1, 16)

    const int NT = HID / 16;   // 128 K-tiles
    for (int tt = 0; tt < NT; tt++) {
        cp_wait<1>();
        __syncthreads();
        if (tt + 2 < NT) LOAD_STAGE((tt + 2) % 3, (tt + 2) * 16)

        const float* Ast = As + (tt % 3) * A_STG;
        const float* Bst = Bs + (tt % 3) * B_STG;
#pragma unroll
        for (int ks = 0; ks < 2; ks++) {
            const int kk = ks * 8 + t;
            uint32_t af[4][4], bf[8][2];
#pragma unroll
            for (int mi = 0; mi < 4; mi++) {
                const float* ap = Ast + (wm + mi * 16 + g) * AST + kk;
                af[mi][0] = __float_as_uint(ap[0]);
                af[mi][1] = __float_as_uint(ap[8 * AST]);
                af[mi][2] = __float_as_uint(ap[4]);
                af[mi][3] = __float_as_uint(ap[8 * AST + 4]);
            }
#pragma unroll
            for (int ni = 0; ni < 8; ni++) {
                const float* bp = Bst + kk * BST + wn + ni * 8 + g;
                bf[ni][0] = __float_as_uint(bp[0]);
                bf[ni][1] = __float_as_uint(bp[4 * BST]);
            }
#pragma unroll
            for (int mi = 0; mi < 4; mi++)
#pragma unroll
                for (int ni = 0; ni < 8; ni++)
                    mma_tf32(acc[mi][ni], af[mi], bf[ni]);
        }
    }
#undef LOAD_STAGE

#pragma unroll
    for (int mi = 0; mi < 4; mi++) {
#pragma unroll
        for (int ni = 0; ni < 8; ni++) {
            const int row = bm + wm + mi * 16 + g;
            const int col = bn + wn + ni * 8 + 2 * t;
            float v0 = acc[mi][ni][0], v1 = acc[mi][ni][1];
            float v2 = acc[mi][ni][2], v3 = acc[mi][ni][3];
            if (round_out) {
                v0 = to_tf32(v0); v1 = to_tf32(v1);
                v2 = to_tf32(v2); v3 = to_tf32(v3);
            }
            *(float2*)&C[(size_t)row * ld + col] = make_float2(v0, v1);
            *(float2*)&C[(size_t)(row + 8) * ld + col] = make_float2(v2, v3);
        }
    }
}

// Fused QKV projection: grid.x routes to Wq (0..7), Wk (8..9), Wv (10..11).
__global__ __launch_bounds__(256, 1) void gemm_qkv(
    const float* __restrict__ x,
    const float* __restrict__ Wq, const float* __restrict__ Wk, const float* __restrict__ Wv,
    float* __restrict__ qp, float* __restrict__ kp, float* __restrict__ vp)
{
    extern __shared__ float sm[];
    const int bx = blockIdx.x;
    const float* B; float* C; int ld; int bn; bool rnd = false;
    if (bx < 8)       { B = Wq; C = qp; ld = QW; bn = bx * 256; }
    else if (bx < 10) { B = Wk; C = kp; ld = KW; bn = (bx - 8) * 256; }
    else              { B = Wv; C = vp; ld = KW; bn = (bx - 10) * 256; rnd = true; }
    gemm_core(x, B, C, ld, blockIdx.y * 128, bn, rnd, sm);
}

__global__ __launch_bounds__(256, 1) void gemm_wo(
    const float* __restrict__ A, const float* __restrict__ W, float* __restrict__ C)
{
    extern __shared__ float sm[];
    gemm_core(A, W, C, HID, blockIdx.y * 128, blockIdx.x * 256, false, sm);
}

// ---------------------------------------------------------------------------
// RoPE in-place, outputs rounded to tf32.
// ---------------------------------------------------------------------------
__global__ void rope_kernel(float* __restrict__ t,
                            const float* __restrict__ cosb,
                            const float* __restrict__ sinb,
                            int heads)
{
    int idx = blockIdx.x * blockDim.x + threadIdx.x;
    int total = ROWS * heads * (HD / 2);
    if (idx >= total) return;
    int d = idx & 63;
    int h = (idx >> 6) % heads;
    int row = idx / (64 * heads);
    int tpos = row & (T_DIM - 1);

    const float c1 = cosb[tpos * HD + d];
    const float s1 = sinb[tpos * HD + d];
    const float c2 = cosb[tpos * HD + d + 64];
    const float s2 = sinb[tpos * HD + d + 64];

    float* p = t + (size_t)row * heads * HD + h * HD;
    float x1 = p[d];
    float x2 = p[d + 64];
    p[d]      = to_tf32(x1 * c1 - x2 * s1);
    p[d + 64] = to_tf32(x2 * c2 + x1 * s2);
}

// ---------------------------------------------------------------------------
// tf32 flash attention with cp.async double-buffered K/V.
// BM=128 (8 warps x m16), BN=64. Inputs pre-rounded; output tf32-rounded.
// ---------------------------------------------------------------------------
#define FBM 128
#define FBN 64
#define KS_ST 132
#define VS_ST 136
#define PS_ST 68
#define K_STG (64 * KS_ST)
#define V_STG (64 * VS_ST)
#define FL_SMEM ((2 * K_STG + 2 * V_STG + 128 * PS_ST) * 4)   // 172032 B

__global__ __launch_bounds__(256, 1) void flash_tf32(
    const float* __restrict__ q, const float* __restrict__ k,
    const float* __restrict__ v, float* __restrict__ o)
{
    extern __shared__ float sm[];
    float* Ks = sm;                      // [2][64][132]
    float* Vs = Ks + 2 * K_STG;          // [2][64][136]
    float* Ps = Vs + 2 * V_STG;          // [128][68]

    const int tid  = threadIdx.x;
    const int lane = tid & 31;
    const int warp = tid >> 5;
    const int g = lane >> 2;
    const int t = lane & 3;
    const int wm = warp * 16;
    const int i0 = (gridDim.x - 1 - (int)blockIdx.x) * FBM;  // heavy CTAs first
    const int h  = blockIdx.y;
    const int b  = blockIdx.z;
    const int kh = h >> 2;

    const float* qbase = q + ((size_t)b * T_DIM + i0) * QW + h * HD;
    const float* kbase = k + ((size_t)b * T_DIM) * KW + kh * HD;
    const float* vbase = v + ((size_t)b * T_DIM) * KW + kh * HD;

    const float scale = 0.08838834764831845f;   // 1/sqrt(128), applied to S

    uint32_t qf[16][4];
    {
        const float* q0 = qbase + (size_t)(wm + g) * QW;
        const float* q8 = qbase + (size_t)(wm + g + 8) * QW;
#pragma unroll
        for (int kc = 0; kc < 16; kc++) {
            int c = kc * 8 + t;
            qf[kc][0] = __float_as_uint(q0[c]);
            qf[kc][1] = __float_as_uint(q8[c]);
            qf[kc][2] = __float_as_uint(q0[c + 4]);
            qf[kc][3] = __float_as_uint(q8[c + 4]);
        }
    }

    float O[16][4];
#pragma unroll
    for (int ni = 0; ni < 16; ni++)
#pragma unroll
        for (int r = 0; r < 4; r++) O[ni][r] = 0.0f;
    float m0 = -INFINITY, m1 = -INFINITY, l0 = 0.0f, l1 = 0.0f;

    const int row0 = i0 + wm + g;
    const int row1 = row0 + 8;
    const int l4 = lane * 4;

#define LOAD_KV(st, j0) { \
    float* Kd = Ks + (st) * K_STG; float* Vd = Vs + (st) * V_STG; \
    _Pragma("unroll") \
    for (int i = 0; i < 8; i++) { \
        const int r = warp + 8 * i; \
        cp16(Kd + r * KS_ST + l4, kbase + (size_t)((j0) + r) * KW + l4); \
        cp16(Vd + r * VS_ST + l4, vbase + (size_t)((j0) + r) * KW + l4); \
    } \
    cp_commit(); }

    const int ntiles = i0 / FBN + 2;
    LOAD_KV(0, 0)

    for (int jt = 0; jt < ntiles; jt++) {
        const int j0 = jt * FBN;
        cp_wait<0>();
        __syncthreads();
        if (jt + 1 < ntiles) LOAD_KV((jt + 1) & 1, j0 + FBN)

        const float* Kst = Ks + (jt & 1) * K_STG;
        const float* Vst = Vs + (jt & 1) * V_STG;

        float S[8][4];
#pragma unroll
        for (int ni = 0; ni < 8; ni++)
#pragma unroll
            for (int r = 0; r < 4; r++) S[ni][r] = 0.0f;

#pragma unroll
        for (int kc = 0; kc < 16; kc++) {
#pragma unroll
            for (int ni = 0; ni < 8; ni++) {
                uint32_t bf[2];
                const float* kp = Kst + (ni * 8 + g) * KS_ST + kc * 8 + t;
                bf[0] = __float_as_uint(kp[0]);
                bf[1] = __float_as_uint(kp[4]);
                mma_tf32(S[ni], qf[kc], bf);
            }
        }

#pragma unroll
        for (int ni = 0; ni < 8; ni++)
#pragma unroll
            for (int r = 0; r < 4; r++) S[ni][r] *= scale;

        if (j0 + FBN > i0) {
#pragma unroll
            for (int ni = 0; ni < 8; ni++) {
                const int col = j0 + ni * 8 + 2 * t;
                if (col     > row0) S[ni][0] = -1e30f;
                if (col + 1 > row0) S[ni][1] = -1e30f;
                if (col     > row1) S[ni][2] = -1e30f;
                if (col + 1 > row1) S[ni][3] = -1e30f;
            }
        }

        float rm0 = -INFINITY, rm1 = -INFINITY;
#pragma unroll
        for (int ni = 0; ni < 8; ni++) {
            rm0 = fmaxf(rm0, fmaxf(S[ni][0], S[ni][1]));
            rm1 = fmaxf(rm1, fmaxf(S[ni][2], S[ni][3]));
        }
        rm0 = fmaxf(rm0, __shfl_xor_sync(0xffffffffu, rm0, 1));
        rm0 = fmaxf(rm0, __shfl_xor_sync(0xffffffffu, rm0, 2));
        rm1 = fmaxf(rm1, __shfl_xor_sync(0xffffffffu, rm1, 1));
        rm1 = fmaxf(rm1, __shfl_xor_sync(0xffffffffu, rm1, 2));

        const float mn0 = fmaxf(m0, rm0);
        const float mn1 = fmaxf(m1, rm1);
        const float a0 = __expf(m0 - mn0);
        const float a1 = __expf(m1 - mn1);
        m0 = mn0; m1 = mn1;

        float rs0 = 0.0f, rs1 = 0.0f;
#pragma unroll
        for (int ni = 0; ni < 8; ni++) {
            S[ni][0] = __expf(S[ni][0] - mn0);
            S[ni][1] = __expf(S[ni][1] - mn0);
            S[ni][2] = __expf(S[ni][2] - mn1);
            S[ni][3] = __expf(S[ni][3] - mn1);
            rs0 += S[ni][0] + S[ni][1];
            rs1 += S[ni][2] + S[ni][3];
        }
        rs0 += __shfl_xor_sync(0xffffffffu, rs0, 1);
        rs0 += __shfl_xor_sync(0xffffffffu, rs0, 2);
        rs1 += __shfl_xor_sync(0xffffffffu, rs1, 1);
        rs1 += __shfl_xor_sync(0xffffffffu, rs1, 2);
        l0 = l0 * a0 + rs0;
        l1 = l1 * a1 + rs1;

#pragma unroll
        for (int ni = 0; ni < 16; ni++) {
            O[ni][0] *= a0; O[ni][1] *= a0;
            O[ni][2] *= a1; O[ni][3] *= a1;
        }

#pragma unroll
        for (int ni = 0; ni < 8; ni++) {
            *(float2*)(Ps + (wm + g) * PS_ST + ni * 8 + 2 * t) =
                make_float2(to_tf32(S[ni][0]), to_tf32(S[ni][1]));
            *(float2*)(Ps + (wm + g + 8) * PS_ST + ni * 8 + 2 * t) =
                make_float2(to_tf32(S[ni][2]), to_tf32(S[ni][3]));
        }
        __syncthreads();

#pragma unroll
        for (int kc = 0; kc < 8; kc++) {
            uint32_t pa[4];
            const float* pp0 = Ps + (wm + g) * PS_ST + kc * 8 + t;
            const float* pp8 = Ps + (wm + g + 8) * PS_ST + kc * 8 + t;
            pa[0] = __float_as_uint(pp0[0]);
            pa[1] = __float_as_uint(pp8[0]);
            pa[2] = __float_as_uint(pp0[4]);
            pa[3] = __float_as_uint(pp8[4]);
#pragma unroll
            for (int ni = 0; ni < 16; ni++) {
                uint32_t bf[2];
                const float* vp = Vst + (kc * 8 + t) * VS_ST + ni * 8 + g;
                bf[0] = __float_as_uint(vp[0]);
                bf[1] = __float_as_uint(vp[4 * VS_ST]);
                mma_tf32(O[ni], pa, bf);
            }
        }
    }
#undef LOAD_KV

    // epilogue: normalize and round to tf32 (feeds Wo GEMM raw)
    const float il0 = 1.0f / l0;
    const float il1 = 1.0f / l1;
    float* ob = o + ((size_t)b * T_DIM + i0) * QW + h * HD;
#pragma unroll
    for (int ni = 0; ni < 16; ni++) {
        *(float2*)(ob + (size_t)(wm + g) * QW + ni * 8 + 2 * t) =
            make_float2(to_tf32(O[ni][0] * il0), to_tf32(O[ni][1] * il0));
        *(float2*)(ob + (size_t)(wm + g + 8) * QW + ni * 8 + 2 * t) =
            make_float2(to_tf32(O[ni][2] * il1), to_tf32(O[ni][3] * il1));
    }
}

// ---------------------------------------------------------------------------
extern "C" void kernel_launch(void* const* d_in, const int* in_sizes, int n_in,
                              void* d_out, int out_size)
{
    const float* x    = (const float*)d_in[0];
    const float* cosb = (const float*)d_in[1];
    const float* sinb = (const float*)d_in[2];
    const float* Wq   = (const float*)d_in[3];
    const float* Wk   = (const float*)d_in[4];
    const float* Wv   = (const float*)d_in[5];
    const float* Wo   = (const float*)d_in[6];
    float* out = (float*)d_out;

    float *qp, *kp, *vp, *ap, *xr, *wq, *wk, *wv, *wo;
    cudaGetSymbolAddress((void**)&qp, g_q);
    cudaGetSymbolAddress((void**)&kp, g_k);
    cudaGetSymbolAddress((void**)&vp, g_v);
    cudaGetSymbolAddress((void**)&ap, g_attn);
    cudaGetSymbolAddress((void**)&xr, g_xr);
    cudaGetSymbolAddress((void**)&wq, g_wq);
    cudaGetSymbolAddress((void**)&wk, g_wk);
    cudaGetSymbolAddress((void**)&wv, g_wv);
    cudaGetSymbolAddress((void**)&wo, g_wo);

    cudaFuncSetAttribute(gemm_qkv, cudaFuncAttributeMaxDynamicSharedMemorySize, GEMM_SMEM);
    cudaFuncSetAttribute(gemm_wo, cudaFuncAttributeMaxDynamicSharedMemorySize, GEMM_SMEM);
    cudaFuncSetAttribute(flash_tf32, cudaFuncAttributeMaxDynamicSharedMemorySize, FL_SMEM);

    // Pre-round GEMM operands to tf32
    round_tf32_kernel<<<(ROWS * HID / 4 + 255) / 256, 256>>>(x, xr, ROWS * HID / 4);
    round_tf32_kernel<<<(HID * QW / 4 + 255) / 256, 256>>>(Wq, wq, HID * QW / 4);
    round_tf32_kernel<<<(HID * KW / 4 + 255) / 256, 256>>>(Wk, wk, HID * KW / 4);
    round_tf32_kernel<<<(HID * KW / 4 + 255) / 256, 256>>>(Wv, wv, HID * KW / 4);
    round_tf32_kernel<<<(QW * HID / 4 + 255) / 256, 256>>>(Wo, wo, QW * HID / 4);

    // Fused QKV projections (12 n-tiles x 32 m-tiles)
    gemm_qkv<<<dim3(12, ROWS / 128), 256, GEMM_SMEM>>>(xr, wq, wk, wv, qp, kp, vp);

    // RoPE on q and k (rounds outputs to tf32)
    {
        int totq = ROWS * NH * (HD / 2);
        rope_kernel<<<(totq + 255) / 256, 256>>>(qp, cosb, sinb, NH);
        int totk = ROWS * NKV * (HD / 2);
        rope_kernel<<<(totk + 255) / 256, 256>>>(kp, cosb, sinb, NKV);
    }

    // Attention
    flash_tf32<<<dim3(T_DIM / FBM, NH, B_DIM), 256, FL_SMEM>>>(qp, kp, vp, ap);

    // Output projection
    gemm_wo<<<dim3(HID / 256, ROWS / 128), 256, GEMM_SMEM>>>(ap, wo, out);
}

// round 7
// speedup vs baseline: 6.4396x; 1.6188x over previous
#include <cuda_runtime.h>
#include <cuda_fp16.h>
#include <math.h>
#include <stdint.h>

#define B_DIM 2
#define T_DIM 2048
#define HID 2048
#define NH 16
#define NKV 4
#define HD 128
#define ROWS (B_DIM * T_DIM)          // 4096
#define QW (NH * HD)                  // 2048
#define KW (NKV * HD)                 // 512

// Scratch (device globals: allocation is forbidden)
__device__ float  g_q[ROWS * QW];     // fp32 Q (pre-rope)
__device__ float  g_k[ROWS * KW];     // fp32 K (pre-rope)
__device__ __half g_xh[ROWS * HID];   // x in half
__device__ __half g_qh[ROWS * QW];    // Q half (post-rope)
__device__ __half g_kh[ROWS * KW];    // K half (post-rope)
__device__ __half g_vh[ROWS * KW];    // V half
__device__ __half g_ah[ROWS * QW];    // attn out half
__device__ __half g_wqh[QW * HID];    // Wq^T half [N][K]
__device__ __half g_wkh[KW * HID];
__device__ __half g_wvh[KW * HID];
__device__ __half g_woh[HID * QW];

__device__ __forceinline__ void mma_f16(float* d, const uint32_t* a, const uint32_t* b) {
    asm volatile(
        "mma.sync.aligned.m16n8k16.row.col.f32.f16.f16.f32 "
        "{%0,%1,%2,%3}, {%4,%5,%6,%7}, {%8,%9}, {%0,%1,%2,%3};"
        : "+f"(d[0]), "+f"(d[1]), "+f"(d[2]), "+f"(d[3])
        : "r"(a[0]), "r"(a[1]), "r"(a[2]), "r"(a[3]), "r"(b[0]), "r"(b[1]));
}

__device__ __forceinline__ void ldmatrix_x4_trans(
    uint32_t& r0, uint32_t& r1, uint32_t& r2, uint32_t& r3, const void* p)
{
    uint32_t a = (uint32_t)__cvta_generic_to_shared(p);
    asm volatile("ldmatrix.sync.aligned.m8n8.x4.trans.shared.b16 {%0,%1,%2,%3}, [%4];"
                 : "=r"(r0), "=r"(r1), "=r"(r2), "=r"(r3) : "r"(a));
}

__device__ __forceinline__ void cp16(void* dst, const void* src) {
    uint32_t d = (uint32_t)__cvta_generic_to_shared(dst);
    asm volatile("cp.async.ca.shared.global [%0], [%1], 16;" :: "r"(d), "l"(src));
}
__device__ __forceinline__ void cp_commit() { asm volatile("cp.async.commit_group;" ::); }
template<int N> __device__ __forceinline__ void cp_wait() {
    asm volatile("cp.async.wait_group %0;" :: "n"(N));
}

// ---------------------------------------------------------------------------
// Pre-passes
// ---------------------------------------------------------------------------
__global__ void cvt_half_kernel(const float* __restrict__ in,
                                __half* __restrict__ out, int n4)
{
    int i = blockIdx.x * blockDim.x + threadIdx.x;
    if (i < n4) {
        float4 v = ((const float4*)in)[i];
        __half2 h0 = __floats2half2_rn(v.x, v.y);
        __half2 h1 = __floats2half2_rn(v.z, v.w);
        ((__half2*)out)[2 * i]     = h0;
        ((__half2*)out)[2 * i + 1] = h1;
    }
}

__global__ __launch_bounds__(256) void transpose_cvt_kernel(
    const float* __restrict__ in, __half* __restrict__ out, int K, int N)
{
    __shared__ float tile[32][33];
    const int tx = threadIdx.x, ty = threadIdx.y;   // 32 x 8
    const int k0 = blockIdx.y * 32, n0 = blockIdx.x * 32;
#pragma unroll
    for (int i = ty; i < 32; i += 8)
        tile[i][tx] = in[(size_t)(k0 + i) * N + n0 + tx];
    __syncthreads();
#pragma unroll
    for (int i = ty; i < 32; i += 8)
        out[(size_t)(n0 + i) * K + k0 + tx] = __float2half_rn(tile[tx][i]);
}

// ---------------------------------------------------------------------------
// fp16 GEMM core: C[128 @bm][128 @bn] = A[*,2048] @ Bt[*,2048]^T
// A half [M][K] row-major, Bt half [N][K] row-major. BK=32, 3-stage cp.async.
// smem strides 40 halves (bank = 20g+t, conflict-free). 8 warps (2x4), 64x32.
// ---------------------------------------------------------------------------
#define HST 40
#define HA_STG (128 * HST)            // halves
#define GH_SMEM (3 * 2 * HA_STG * 2)  // 61440 B

__device__ __forceinline__ void gemm_h_core(
    const __half* __restrict__ A, const __half* __restrict__ Bt,
    float* __restrict__ Cf, __half* __restrict__ Ch,
    int ldc, int bm, int bn, __half* smh)
{
    __half* Ash = smh;
    __half* Bsh = smh + 3 * HA_STG;
    const int tid = threadIdx.x, lane = tid & 31, warp = tid >> 5;
    const int g = lane >> 2, tq = lane & 3;
    const int wm = (warp >> 2) * 64, wn = (warp & 3) * 32;

    float acc[4][4][4];
#pragma unroll
    for (int mi = 0; mi < 4; mi++)
#pragma unroll
        for (int ni = 0; ni < 4; ni++)
#pragma unroll
            for (int r = 0; r < 4; r++) acc[mi][ni][r] = 0.0f;

#define LOAD_STAGE(st, k0) { \
    __half* Ad = Ash + (st) * HA_STG; \
    __half* Bd = Bsh + (st) * HA_STG; \
    _Pragma("unroll") \
    for (int j = 0; j < 2; j++) { \
        int i = tid + 256 * j; int row = i >> 2; int c = i & 3; \
        cp16(Ad + row * HST + c * 8, A + (size_t)(bm + row) * HID + (k0) + c * 8); \
        cp16(Bd + row * HST + c * 8, Bt + (size_t)(bn + row) * HID + (k0) + c * 8); \
    } \
    cp_commit(); }

    LOAD_STAGE(0, 0)
    LOAD_STAGE(1, 32)

    const int NT = HID / 32;   // 64
    for (int t = 0; t < NT; t++) {
        cp_wait<1>();
        __syncthreads();
        if (t + 2 < NT) LOAD_STAGE((t + 2) % 3, (t + 2) * 32)

        const __half* Ast = Ash + (t % 3) * HA_STG;
        const __half* Bst = Bsh + (t % 3) * HA_STG;
#pragma unroll
        for (int ks = 0; ks < 2; ks++) {
            const int kh = ks * 16 + 2 * tq;
            uint32_t af[4][4], bf[4][2];
#pragma unroll
            for (int mi = 0; mi < 4; mi++) {
                const __half* ap = Ast + (wm + mi * 16 + g) * HST + kh;
                af[mi][0] = *(const uint32_t*)(ap);
                af[mi][1] = *(const uint32_t*)(ap + 8 * HST);
                af[mi][2] = *(const uint32_t*)(ap + 8);
                af[mi][3] = *(const uint32_t*)(ap + 8 * HST + 8);
            }
#pragma unroll
            for (int ni = 0; ni < 4; ni++) {
                const __half* bp = Bst + (wn + ni * 8 + g) * HST + kh;
                bf[ni][0] = *(const uint32_t*)(bp);
                bf[ni][1] = *(const uint32_t*)(bp + 8);
            }
#pragma unroll
            for (int mi = 0; mi < 4; mi++)
#pragma unroll
                for (int ni = 0; ni < 4; ni++)
                    mma_f16(acc[mi][ni], af[mi], bf[ni]);
        }
    }
#undef LOAD_STAGE

#pragma unroll
    for (int mi = 0; mi < 4; mi++) {
#pragma unroll
        for (int ni = 0; ni < 4; ni++) {
            const int row = bm + wm + mi * 16 + g;
            const int col = bn + wn + ni * 8 + 2 * tq;
            if (Ch) {
                *(__half2*)&Ch[(size_t)row * ldc + col] =
                    __floats2half2_rn(acc[mi][ni][0], acc[mi][ni][1]);
                *(__half2*)&Ch[(size_t)(row + 8) * ldc + col] =
                    __floats2half2_rn(acc[mi][ni][2], acc[mi][ni][3]);
            } else {
                *(float2*)&Cf[(size_t)row * ldc + col] =
                    make_float2(acc[mi][ni][0], acc[mi][ni][1]);
                *(float2*)&Cf[(size_t)(row + 8) * ldc + col] =
                    make_float2(acc[mi][ni][2], acc[mi][ni][3]);
            }
        }
    }
}

// Fused QKV: bx 0..15 -> Q (fp32), 16..19 -> K (fp32), 20..23 -> V (half)
__global__ __launch_bounds__(256, 2) void gemm_qkv_h(
    const __half* __restrict__ x,
    const __half* __restrict__ WqT, const __half* __restrict__ WkT,
    const __half* __restrict__ WvT,
    float* __restrict__ qp, float* __restrict__ kp, __half* __restrict__ vp)
{
    extern __shared__ __half smh[];
    const int bx = blockIdx.x;
    const __half* Bt; float* Cf = nullptr; __half* Ch = nullptr; int ldc; int bn;
    if (bx < 16)      { Bt = WqT; Cf = qp; ldc = QW; bn = bx * 128; }
    else if (bx < 20) { Bt = WkT; Cf = kp; ldc = KW; bn = (bx - 16) * 128; }
    else              { Bt = WvT; Ch = vp; ldc = KW; bn = (bx - 20) * 128; }
    gemm_h_core(x, Bt, Cf, Ch, ldc, blockIdx.y * 128, bn, smh);
}

__global__ __launch_bounds__(256, 2) void gemm_wo_h(
    const __half* __restrict__ A, const __half* __restrict__ WoT,
    float* __restrict__ C)
{
    extern __shared__ __half smh[];
    gemm_h_core(A, WoT, C, nullptr, HID, blockIdx.y * 128, blockIdx.x * 128, smh);
}

// ---------------------------------------------------------------------------
// RoPE: fp32 in -> half out
// ---------------------------------------------------------------------------
__global__ void rope_h_kernel(const float* __restrict__ in, __half* __restrict__ out,
                              const float* __restrict__ cosb,
                              const float* __restrict__ sinb, int heads)
{
    int idx = blockIdx.x * blockDim.x + threadIdx.x;
    int total = ROWS * heads * (HD / 2);
    if (idx >= total) return;
    int d = idx & 63;
    int h = (idx >> 6) % heads;
    int row = idx / (64 * heads);
    int tpos = row & (T_DIM - 1);

    const float c1 = cosb[tpos * HD + d];
    const float s1 = sinb[tpos * HD + d];
    const float c2 = cosb[tpos * HD + d + 64];
    const float s2 = sinb[tpos * HD + d + 64];

    const float* p = in + (size_t)row * heads * HD + h * HD;
    __half* q = out + (size_t)row * heads * HD + h * HD;
    float x1 = p[d];
    float x2 = p[d + 64];
    q[d]      = __float2half_rn(x1 * c1 - x2 * s1);
    q[d + 64] = __float2half_rn(x2 * c2 + x1 * s2);
}

// ---------------------------------------------------------------------------
// fp16 flash attention. BM=128 (8 warps x m16), BN=64, double-buffered K/V.
// K/V smem [64][136] halves; P [128][72] halves; V frags via ldmatrix.trans.
// ---------------------------------------------------------------------------
#define FBM 128
#define FBN 64
#define KVST 136                       // halves per K/V row
#define PST 72                         // halves per P row
#define KV_STG (64 * KVST)             // 8704 halves per stage
#define FL_SMEM ((4 * KV_STG + 128 * PST) * 2)   // 88064 B

__global__ __launch_bounds__(256, 1) void flash_h16(
    const __half* __restrict__ q, const __half* __restrict__ k,
    const __half* __restrict__ v, __half* __restrict__ o)
{
    extern __shared__ __half smh[];
    __half* Ks = smh;                  // [2][64][136]
    __half* Vs = Ks + 2 * KV_STG;      // [2][64][136]
    __half* Ps = Vs + 2 * KV_STG;      // [128][72]

    const int tid  = threadIdx.x;
    const int lane = tid & 31;
    const int warp = tid >> 5;
    const int g = lane >> 2;
    const int tq = lane & 3;
    const int wm = warp * 16;
    const int i0 = (gridDim.x - 1 - (int)blockIdx.x) * FBM;   // heavy CTAs first
    const int h  = blockIdx.y;
    const int b  = blockIdx.z;
    const int kh = h >> 2;

    const __half* qbase = q + ((size_t)b * T_DIM + i0) * QW + h * HD;
    const __half* kbase = k + ((size_t)b * T_DIM) * KW + kh * HD;
    const __half* vbase = v + ((size_t)b * T_DIM) * KW + kh * HD;

    const float scale = 0.08838834764831845f;   // 1/sqrt(128)

    // Q fragments: 8 k16-chunks covering d=128
    uint32_t qf[8][4];
    {
        const __half* q0 = qbase + (size_t)(wm + g) * QW;
        const __half* q8 = q0 + (size_t)8 * QW;
#pragma unroll
        for (int kc = 0; kc < 8; kc++) {
            const int c = kc * 16 + 2 * tq;
            qf[kc][0] = *(const uint32_t*)(q0 + c);
            qf[kc][1] = *(const uint32_t*)(q8 + c);
            qf[kc][2] = *(const uint32_t*)(q0 + c + 8);
            qf[kc][3] = *(const uint32_t*)(q8 + c + 8);
        }
    }

    float O[16][4];
#pragma unroll
    for (int ni = 0; ni < 16; ni++)
#pragma unroll
        for (int r = 0; r < 4; r++) O[ni][r] = 0.0f;
    float m0 = -INFINITY, m1 = -INFINITY, l0 = 0.0f, l1 = 0.0f;

    const int row0 = i0 + wm + g;
    const int row1 = row0 + 8;

#define LOAD_KV(st, j0) { \
    __half* Kd = Ks + (st) * KV_STG; \
    __half* Vd = Vs + (st) * KV_STG; \
    _Pragma("unroll") \
    for (int j = 0; j < 4; j++) { \
        int i = tid + 256 * j; int row = i >> 4; int c = i & 15; \
        cp16(Kd + row * KVST + c * 8, kbase + (size_t)((j0) + row) * KW + c * 8); \
        cp16(Vd + row * KVST + c * 8, vbase + (size_t)((j0) + row) * KW + c * 8); \
    } \
    cp_commit(); }

    const int ntiles = i0 / FBN + 2;
    LOAD_KV(0, 0)

    for (int jt = 0; jt < ntiles; jt++) {
        const int j0 = jt * FBN;
        cp_wait<0>();
        __syncthreads();
        if (jt + 1 < ntiles) LOAD_KV((jt + 1) & 1, j0 + FBN)

        const __half* Kst = Ks + (jt & 1) * KV_STG;
        const __half* Vst = Vs + (jt & 1) * KV_STG;

        // S = Q @ K^T : 8 k16-chunks x 8 n8-tiles
        float S[8][4];
#pragma unroll
        for (int ni = 0; ni < 8; ni++)
#pragma unroll
            for (int r = 0; r < 4; r++) S[ni][r] = 0.0f;

#pragma unroll
        for (int kc = 0; kc < 8; kc++) {
#pragma unroll
            for (int ni = 0; ni < 8; ni++) {
                uint32_t bf[2];
                const __half* kp = Kst + (ni * 8 + g) * KVST + kc * 16 + 2 * tq;
                bf[0] = *(const uint32_t*)(kp);
                bf[1] = *(const uint32_t*)(kp + 8);
                mma_f16(S[ni], qf[kc], bf);
            }
        }

#pragma unroll
        for (int ni = 0; ni < 8; ni++)
#pragma unroll
            for (int r = 0; r < 4; r++) S[ni][r] *= scale;

        if (j0 + FBN > i0) {
#pragma unroll
            for (int ni = 0; ni < 8; ni++) {
                const int col = j0 + ni * 8 + 2 * tq;
                if (col     > row0) S[ni][0] = -1e30f;
                if (col + 1 > row0) S[ni][1] = -1e30f;
                if (col     > row1) S[ni][2] = -1e30f;
                if (col + 1 > row1) S[ni][3] = -1e30f;
            }
        }

        // online softmax
        float rm0 = -INFINITY, rm1 = -INFINITY;
#pragma unroll
        for (int ni = 0; ni < 8; ni++) {
            rm0 = fmaxf(rm0, fmaxf(S[ni][0], S[ni][1]));
            rm1 = fmaxf(rm1, fmaxf(S[ni][2], S[ni][3]));
        }
        rm0 = fmaxf(rm0, __shfl_xor_sync(0xffffffffu, rm0, 1));
        rm0 = fmaxf(rm0, __shfl_xor_sync(0xffffffffu, rm0, 2));
        rm1 = fmaxf(rm1, __shfl_xor_sync(0xffffffffu, rm1, 1));
        rm1 = fmaxf(rm1, __shfl_xor_sync(0xffffffffu, rm1, 2));

        const float mn0 = fmaxf(m0, rm0);
        const float mn1 = fmaxf(m1, rm1);
        const float a0 = __expf(m0 - mn0);
        const float a1 = __expf(m1 - mn1);
        m0 = mn0; m1 = mn1;

        float rs0 = 0.0f, rs1 = 0.0f;
#pragma unroll
        for (int ni = 0; ni < 8; ni++) {
            S[ni][0] = __expf(S[ni][0] - mn0);
            S[ni][1] = __expf(S[ni][1] - mn0);
            S[ni][2] = __expf(S[ni][2] - mn1);
            S[ni][3] = __expf(S[ni][3] - mn1);
            rs0 += S[ni][0] + S[ni][1];
            rs1 += S[ni][2] + S[ni][3];
        }
        rs0 += __shfl_xor_sync(0xffffffffu, rs0, 1);
        rs0 += __shfl_xor_sync(0xffffffffu, rs0, 2);
        rs1 += __shfl_xor_sync(0xffffffffu, rs1, 1);
        rs1 += __shfl_xor_sync(0xffffffffu, rs1, 2);
        l0 = l0 * a0 + rs0;
        l1 = l1 * a1 + rs1;

#pragma unroll
        for (int ni = 0; ni < 16; ni++) {
            O[ni][0] *= a0; O[ni][1] *= a0;
            O[ni][2] *= a1; O[ni][3] *= a1;
        }

        // store P as half
#pragma unroll
        for (int ni = 0; ni < 8; ni++) {
            *(__half2*)(Ps + (wm + g) * PST + ni * 8 + 2 * tq) =
                __floats2half2_rn(S[ni][0], S[ni][1]);
            *(__half2*)(Ps + (wm + g + 8) * PST + ni * 8 + 2 * tq) =
                __floats2half2_rn(S[ni][2], S[ni][3]);
        }
        __syncthreads();

        // O += P @ V : 4 k16-chunks (64 kv), 8 ldmatrix.x4 each covering n16
        const int lrow = (lane & 7) + 8 * ((lane >> 3) & 1);
        const int lcol = 8 * (lane >> 4);
#pragma unroll
        for (int kc = 0; kc < 4; kc++) {
            uint32_t pa[4];
            const __half* pp0 = Ps + (wm + g) * PST + kc * 16 + 2 * tq;
            const __half* pp8 = pp0 + 8 * PST;
            pa[0] = *(const uint32_t*)(pp0);
            pa[1] = *(const uint32_t*)(pp8);
            pa[2] = *(const uint32_t*)(pp0 + 8);
            pa[3] = *(const uint32_t*)(pp8 + 8);
            const __half* vrow = Vst + (kc * 16 + lrow) * KVST + lcol;
#pragma unroll
            for (int ni2 = 0; ni2 < 8; ni2++) {
                uint32_t r0, r1, r2, r3;
                ldmatrix_x4_trans(r0, r1, r2, r3, vrow + ni2 * 16);
                uint32_t b0[2] = {r0, r1}, b1[2] = {r2, r3};
                mma_f16(O[2 * ni2],     pa, b0);
                mma_f16(O[2 * ni2 + 1], pa, b1);
            }
        }
    }
#undef LOAD_KV

    // epilogue: normalize, write half attn
    const float il0 = 1.0f / l0;
    const float il1 = 1.0f / l1;
    __half* ob = o + ((size_t)b * T_DIM + i0) * QW + h * HD;
#pragma unroll
    for (int ni = 0; ni < 16; ni++) {
        *(__half2*)(ob + (size_t)(wm + g) * QW + ni * 8 + 2 * tq) =
            __floats2half2_rn(O[ni][0] * il0, O[ni][1] * il0);
        *(__half2*)(ob + (size_t)(wm + g + 8) * QW + ni * 8 + 2 * tq) =
            __floats2half2_rn(O[ni][2] * il1, O[ni][3] * il1);
    }
}

// ---------------------------------------------------------------------------
extern "C" void kernel_launch(void* const* d_in, const int* in_sizes, int n_in,
                              void* d_out, int out_size)
{
    const float* x    = (const float*)d_in[0];
    const float* cosb = (const float*)d_in[1];
    const float* sinb = (const float*)d_in[2];
    const float* Wq   = (const float*)d_in[3];
    const float* Wk   = (const float*)d_in[4];
    const float* Wv   = (const float*)d_in[5];
    const float* Wo   = (const float*)d_in[6];
    float* out = (float*)d_out;

    float *qp, *kp;
    __half *xh, *qh, *khh, *vh, *ah, *wqh, *wkh, *wvh, *woh;
    cudaGetSymbolAddress((void**)&qp, g_q);
    cudaGetSymbolAddress((void**)&kp, g_k);
    cudaGetSymbolAddress((void**)&xh, g_xh);
    cudaGetSymbolAddress((void**)&qh, g_qh);
    cudaGetSymbolAddress((void**)&khh, g_kh);
    cudaGetSymbolAddress((void**)&vh, g_vh);
    cudaGetSymbolAddress((void**)&ah, g_ah);
    cudaGetSymbolAddress((void**)&wqh, g_wqh);
    cudaGetSymbolAddress((void**)&wkh, g_wkh);
    cudaGetSymbolAddress((void**)&wvh, g_wvh);
    cudaGetSymbolAddress((void**)&woh, g_woh);

    cudaFuncSetAttribute(gemm_qkv_h, cudaFuncAttributeMaxDynamicSharedMemorySize, GH_SMEM);
    cudaFuncSetAttribute(gemm_wo_h, cudaFuncAttributeMaxDynamicSharedMemorySize, GH_SMEM);
    cudaFuncSetAttribute(flash_h16, cudaFuncAttributeMaxDynamicSharedMemorySize, FL_SMEM);

    // Pre-passes: x -> half; weights -> transposed half
    cvt_half_kernel<<<(ROWS * HID / 4 + 255) / 256, 256>>>(x, xh, ROWS * HID / 4);
    transpose_cvt_kernel<<<dim3(QW / 32, HID / 32), dim3(32, 8)>>>(Wq, wqh, HID, QW);
    transpose_cvt_kernel<<<dim3(KW / 32, HID / 32), dim3(32, 8)>>>(Wk, wkh, HID, KW);
    transpose_cvt_kernel<<<dim3(KW / 32, HID / 32), dim3(32, 8)>>>(Wv, wvh, HID, KW);
    transpose_cvt_kernel<<<dim3(HID / 32, QW / 32), dim3(32, 8)>>>(Wo, woh, QW, HID);

    // QKV projections (fp16 tensor cores)
    gemm_qkv_h<<<dim3(24, ROWS / 128), 256, GH_SMEM>>>(xh, wqh, wkh, wvh, qp, kp, vh);

    // RoPE: fp32 -> half
    {
        int totq = ROWS * NH * (HD / 2);
        rope_h_kernel<<<(totq + 255) / 256, 256>>>(qp, qh, cosb, sinb, NH);
        int totk = ROWS * NKV * (HD / 2);
        rope_h_kernel<<<(totk + 255) / 256, 256>>>(kp, khh, cosb, sinb, NKV);
    }

    // Attention (fp16)
    flash_h16<<<dim3(T_DIM / FBM, NH, B_DIM), 256, FL_SMEM>>>(qh, khh, vh, ah);

    // Output projection (fp16)
    gemm_wo_h<<<dim3(HID / 128, ROWS / 128), 256, GH_SMEM>>>(ah, woh, out);
}

// round 8
// speedup vs baseline: 7.4788x; 1.1614x over previous
#include <cuda_runtime.h>
#include <cuda_fp16.h>
#include <math.h>
#include <stdint.h>

#define B_DIM 2
#define T_DIM 2048
#define HID 2048
#define NH 16
#define NKV 4
#define HD 128
#define ROWS (B_DIM * T_DIM)          // 4096
#define QW (NH * HD)                  // 2048
#define KW (NKV * HD)                 // 512

// Scratch (device globals: allocation is forbidden)
__device__ float  g_q[ROWS * QW];     // fp32 Q (pre-rope)
__device__ float  g_k[ROWS * KW];     // fp32 K (pre-rope)
__device__ __half g_xh[ROWS * HID];   // x in half
__device__ __half g_qh[ROWS * QW];    // Q half (post-rope)
__device__ __half g_kh[ROWS * KW];    // K half (post-rope)
__device__ __half g_vh[ROWS * KW];    // V half
__device__ __half g_ah[ROWS * QW];    // attn out half
__device__ __half g_wqh[QW * HID];    // Wq^T half [N][K]
__device__ __half g_wkh[KW * HID];
__device__ __half g_wvh[KW * HID];
__device__ __half g_woh[HID * QW];

__device__ __forceinline__ void mma_f16(float* d, const uint32_t* a, const uint32_t* b) {
    asm volatile(
        "mma.sync.aligned.m16n8k16.row.col.f32.f16.f16.f32 "
        "{%0,%1,%2,%3}, {%4,%5,%6,%7}, {%8,%9}, {%0,%1,%2,%3};"
        : "+f"(d[0]), "+f"(d[1]), "+f"(d[2]), "+f"(d[3])
        : "r"(a[0]), "r"(a[1]), "r"(a[2]), "r"(a[3]), "r"(b[0]), "r"(b[1]));
}

__device__ __forceinline__ void ldmx4(
    uint32_t& r0, uint32_t& r1, uint32_t& r2, uint32_t& r3, const void* p)
{
    uint32_t a = (uint32_t)__cvta_generic_to_shared(p);
    asm volatile("ldmatrix.sync.aligned.m8n8.x4.shared.b16 {%0,%1,%2,%3}, [%4];"
                 : "=r"(r0), "=r"(r1), "=r"(r2), "=r"(r3) : "r"(a));
}
__device__ __forceinline__ void ldmx4_trans(
    uint32_t& r0, uint32_t& r1, uint32_t& r2, uint32_t& r3, const void* p)
{
    uint32_t a = (uint32_t)__cvta_generic_to_shared(p);
    asm volatile("ldmatrix.sync.aligned.m8n8.x4.trans.shared.b16 {%0,%1,%2,%3}, [%4];"
                 : "=r"(r0), "=r"(r1), "=r"(r2), "=r"(r3) : "r"(a));
}

__device__ __forceinline__ uint32_t pack2(float a, float b) {
    __half2 h = __floats2half2_rn(a, b);
    return *(uint32_t*)&h;
}

__device__ __forceinline__ void cp16(void* dst, const void* src) {
    uint32_t d = (uint32_t)__cvta_generic_to_shared(dst);
    asm volatile("cp.async.ca.shared.global [%0], [%1], 16;" :: "r"(d), "l"(src));
}
__device__ __forceinline__ void cp_commit() { asm volatile("cp.async.commit_group;" ::); }
template<int N> __device__ __forceinline__ void cp_wait() {
    asm volatile("cp.async.wait_group %0;" :: "n"(N));
}

// ---------------------------------------------------------------------------
// Pre-passes
// ---------------------------------------------------------------------------
__global__ void cvt_half_kernel(const float* __restrict__ in,
                                __half* __restrict__ out, int n4)
{
    int i = blockIdx.x * blockDim.x + threadIdx.x;
    if (i < n4) {
        float4 v = ((const float4*)in)[i];
        ((__half2*)out)[2 * i]     = __floats2half2_rn(v.x, v.y);
        ((__half2*)out)[2 * i + 1] = __floats2half2_rn(v.z, v.w);
    }
}

__global__ __launch_bounds__(256) void transpose_cvt_kernel(
    const float* __restrict__ in, __half* __restrict__ out, int K, int N)
{
    __shared__ float tile[32][33];
    const int tx = threadIdx.x, ty = threadIdx.y;   // 32 x 8
    const int k0 = blockIdx.y * 32, n0 = blockIdx.x * 32;
#pragma unroll
    for (int i = ty; i < 32; i += 8)
        tile[i][tx] = in[(size_t)(k0 + i) * N + n0 + tx];
    __syncthreads();
#pragma unroll
    for (int i = ty; i < 32; i += 8)
        out[(size_t)(n0 + i) * K + k0 + tx] = __float2half_rn(tile[tx][i]);
}

// ---------------------------------------------------------------------------
// fp16 GEMM core: C[128 @bm][128 @bn] = A[*,2048] @ Bt[*,2048]^T
// ldmatrix fragment loads. BK=32, 3-stage cp.async. 8 warps (2x4), 64x32.
// ---------------------------------------------------------------------------
#define HST 40
#define HA_STG (128 * HST)            // halves
#define GH_SMEM (3 * 2 * HA_STG * 2)  // 61440 B

__device__ __forceinline__ void gemm_h_core(
    const __half* __restrict__ A, const __half* __restrict__ Bt,
    float* __restrict__ Cf, __half* __restrict__ Ch,
    int ldc, int bm, int bn, __half* smh)
{
    __half* Ash = smh;
    __half* Bsh = smh + 3 * HA_STG;
    const int tid = threadIdx.x, lane = tid & 31, warp = tid >> 5;
    const int g = lane >> 2, tq = lane & 3;
    const int wm = (warp >> 2) * 64, wn = (warp & 3) * 32;
    const int lr = lane & 15;               // ldmatrix row within 16
    const int lc = (lane >> 4) * 8;         // ldmatrix k-offset

    float acc[4][4][4];
#pragma unroll
    for (int mi = 0; mi < 4; mi++)
#pragma unroll
        for (int ni = 0; ni < 4; ni++)
#pragma unroll
            for (int r = 0; r < 4; r++) acc[mi][ni][r] = 0.0f;

#define LOAD_STAGE(st, k0) { \
    __half* Ad = Ash + (st) * HA_STG; \
    __half* Bd = Bsh + (st) * HA_STG; \
    _Pragma("unroll") \
    for (int j = 0; j < 2; j++) { \
        int i = tid + 256 * j; int row = i >> 2; int c = i & 3; \
        cp16(Ad + row * HST + c * 8, A + (size_t)(bm + row) * HID + (k0) + c * 8); \
        cp16(Bd + row * HST + c * 8, Bt + (size_t)(bn + row) * HID + (k0) + c * 8); \
    } \
    cp_commit(); }

    LOAD_STAGE(0, 0)
    LOAD_STAGE(1, 32)

    const int NT = HID / 32;   // 64
    for (int t = 0; t < NT; t++) {
        cp_wait<1>();
        __syncthreads();
        if (t + 2 < NT) LOAD_STAGE((t + 2) % 3, (t + 2) * 32)

        const __half* Ast = Ash + (t % 3) * HA_STG;
        const __half* Bst = Bsh + (t % 3) * HA_STG;
#pragma unroll
        for (int ks = 0; ks < 2; ks++) {
            const int kh = ks * 16 + lc;
            uint32_t af[4][4], bf[4][2];
#pragma unroll
            for (int mi = 0; mi < 4; mi++)
                ldmx4(af[mi][0], af[mi][1], af[mi][2], af[mi][3],
                      Ast + (wm + mi * 16 + lr) * HST + kh);
#pragma unroll
            for (int nj = 0; nj < 2; nj++) {
                uint32_t r0, r1, r2, r3;
                ldmx4(r0, r1, r2, r3, Bst + (wn + nj * 16 + lr) * HST + kh);
                bf[2 * nj][0] = r0;     bf[2 * nj][1] = r2;
                bf[2 * nj + 1][0] = r1; bf[2 * nj + 1][1] = r3;
            }
#pragma unroll
            for (int mi = 0; mi < 4; mi++)
#pragma unroll
                for (int ni = 0; ni < 4; ni++)
                    mma_f16(acc[mi][ni], af[mi], bf[ni]);
        }
    }
#undef LOAD_STAGE

#pragma unroll
    for (int mi = 0; mi < 4; mi++) {
#pragma unroll
        for (int ni = 0; ni < 4; ni++) {
            const int row = bm + wm + mi * 16 + g;
            const int col = bn + wn + ni * 8 + 2 * tq;
            if (Ch) {
                *(__half2*)&Ch[(size_t)row * ldc + col] =
                    __floats2half2_rn(acc[mi][ni][0], acc[mi][ni][1]);
                *(__half2*)&Ch[(size_t)(row + 8) * ldc + col] =
                    __floats2half2_rn(acc[mi][ni][2], acc[mi][ni][3]);
            } else {
                *(float2*)&Cf[(size_t)row * ldc + col] =
                    make_float2(acc[mi][ni][0], acc[mi][ni][1]);
                *(float2*)&Cf[(size_t)(row + 8) * ldc + col] =
                    make_float2(acc[mi][ni][2], acc[mi][ni][3]);
            }
        }
    }
}

// Fused QKV: bx 0..15 -> Q (fp32), 16..19 -> K (fp32), 20..23 -> V (half)
__global__ __launch_bounds__(256, 2) void gemm_qkv_h(
    const __half* __restrict__ x,
    const __half* __restrict__ WqT, const __half* __restrict__ WkT,
    const __half* __restrict__ WvT,
    float* __restrict__ qp, float* __restrict__ kp, __half* __restrict__ vp)
{
    extern __shared__ __half smh[];
    const int bx = blockIdx.x;
    const __half* Bt; float* Cf = nullptr; __half* Ch = nullptr; int ldc; int bn;
    if (bx < 16)      { Bt = WqT; Cf = qp; ldc = QW; bn = bx * 128; }
    else if (bx < 20) { Bt = WkT; Cf = kp; ldc = KW; bn = (bx - 16) * 128; }
    else              { Bt = WvT; Ch = vp; ldc = KW; bn = (bx - 20) * 128; }
    gemm_h_core(x, Bt, Cf, Ch, ldc, blockIdx.y * 128, bn, smh);
}

__global__ __launch_bounds__(256, 2) void gemm_wo_h(
    const __half* __restrict__ A, const __half* __restrict__ WoT,
    float* __restrict__ C)
{
    extern __shared__ __half smh[];
    gemm_h_core(A, WoT, C, nullptr, HID, blockIdx.y * 128, blockIdx.x * 128, smh);
}

// ---------------------------------------------------------------------------
// RoPE (q and k in one launch): fp32 in -> half out
// ---------------------------------------------------------------------------
__global__ void rope_both_kernel(const float* __restrict__ qin, __half* __restrict__ qout,
                                 const float* __restrict__ kin, __half* __restrict__ kout,
                                 const float* __restrict__ cosb,
                                 const float* __restrict__ sinb)
{
    int idx = blockIdx.x * blockDim.x + threadIdx.x;
    const int totq = ROWS * NH * (HD / 2);
    const int totk = ROWS * NKV * (HD / 2);
    if (idx >= totq + totk) return;

    const float* in; __half* out; int heads;
    if (idx < totq) { in = qin; out = qout; heads = NH; }
    else            { in = kin; out = kout; heads = NKV; idx -= totq; }

    int d = idx & 63;
    int h = (idx >> 6) % heads;
    int row = idx / (64 * heads);
    int tpos = row & (T_DIM - 1);

    const float c1 = cosb[tpos * HD + d];
    const float s1 = sinb[tpos * HD + d];
    const float c2 = cosb[tpos * HD + d + 64];
    const float s2 = sinb[tpos * HD + d + 64];

    const float* p = in + (size_t)row * heads * HD + h * HD;
    __half* q = out + (size_t)row * heads * HD + h * HD;
    float x1 = p[d];
    float x2 = p[d + 64];
    q[d]      = __float2half_rn(x1 * c1 - x2 * s1);
    q[d + 64] = __float2half_rn(x2 * c2 + x1 * s2);
}

// ---------------------------------------------------------------------------
// fp16 flash attention, FA2-style register P reuse (no P smem, one sync/tile).
// BM=128 (8 warps x m16), BN=128, double-buffered K/V in smem.
// ---------------------------------------------------------------------------
#define FBM 128
#define FBN 128
#define KVST 136                       // halves per K/V row
#define KV_STG (128 * KVST)            // halves per stage
#define FL_SMEM (4 * KV_STG * 2)       // 139264 B

__global__ __launch_bounds__(256, 1) void flash_h16(
    const __half* __restrict__ q, const __half* __restrict__ k,
    const __half* __restrict__ v, __half* __restrict__ o)
{
    extern __shared__ __half smh[];
    __half* Ks = smh;                  // [2][128][136]
    __half* Vs = Ks + 2 * KV_STG;      // [2][128][136]

    const int tid  = threadIdx.x;
    const int lane = tid & 31;
    const int warp = tid >> 5;
    const int g = lane >> 2;
    const int tq = lane & 3;
    const int wm = warp * 16;
    const int lr = lane & 15;
    const int lc = (lane >> 4) * 8;
    const int i0 = (gridDim.x - 1 - (int)blockIdx.x) * FBM;   // heavy CTAs first
    const int h  = blockIdx.y;
    const int b  = blockIdx.z;
    const int kh = h >> 2;

    const __half* qbase = q + ((size_t)b * T_DIM + i0) * QW + h * HD;
    const __half* kbase = k + ((size_t)b * T_DIM) * KW + kh * HD;
    const __half* vbase = v + ((size_t)b * T_DIM) * KW + kh * HD;

    const float scale = 0.08838834764831845f;   // 1/sqrt(128)

    // Q fragments: 8 k16-chunks covering d=128
    uint32_t qf[8][4];
    {
        const __half* q0 = qbase + (size_t)(wm + g) * QW;
        const __half* q8 = q0 + (size_t)8 * QW;
#pragma unroll
        for (int kc = 0; kc < 8; kc++) {
            const int c = kc * 16 + 2 * tq;
            qf[kc][0] = *(const uint32_t*)(q0 + c);
            qf[kc][1] = *(const uint32_t*)(q8 + c);
            qf[kc][2] = *(const uint32_t*)(q0 + c + 8);
            qf[kc][3] = *(const uint32_t*)(q8 + c + 8);
        }
    }

    float O[16][4];
#pragma unroll
    for (int ni = 0; ni < 16; ni++)
#pragma unroll
        for (int r = 0; r < 4; r++) O[ni][r] = 0.0f;
    float m0 = -INFINITY, m1 = -INFINITY, l0 = 0.0f, l1 = 0.0f;

    const int row0 = i0 + wm + g;
    const int row1 = row0 + 8;

#define LOAD_KV(st, j0) { \
    __half* Kd = Ks + (st) * KV_STG; \
    __half* Vd = Vs + (st) * KV_STG; \
    _Pragma("unroll") \
    for (int j = 0; j < 8; j++) { \
        int i = tid + 256 * j; int row = i >> 4; int c = i & 15; \
        cp16(Kd + row * KVST + c * 8, kbase + (size_t)((j0) + row) * KW + c * 8); \
        cp16(Vd + row * KVST + c * 8, vbase + (size_t)((j0) + row) * KW + c * 8); \
    } \
    cp_commit(); }

    const int ntiles = i0 / FBN + 1;
    LOAD_KV(0, 0)

    for (int jt = 0; jt < ntiles; jt++) {
        const int j0 = jt * FBN;
        cp_wait<0>();
        __syncthreads();
        if (jt + 1 < ntiles) LOAD_KV((jt + 1) & 1, j0 + FBN)

        const __half* Kst = Ks + (jt & 1) * KV_STG;
        const __half* Vst = Vs + (jt & 1) * KV_STG;

        // S = Q @ K^T : 8 k16-chunks x 16 n8-tiles (K frags via ldmatrix)
        float S[16][4];
#pragma unroll
        for (int ni = 0; ni < 16; ni++)
#pragma unroll
            for (int r = 0; r < 4; r++) S[ni][r] = 0.0f;

#pragma unroll
        for (int kc = 0; kc < 8; kc++) {
#pragma unroll
            for (int nj = 0; nj < 8; nj++) {
                uint32_t r0, r1, r2, r3;
                ldmx4(r0, r1, r2, r3,
                      Kst + (nj * 16 + lr) * KVST + kc * 16 + lc);
                uint32_t b0[2] = {r0, r2}, b1[2] = {r1, r3};
                mma_f16(S[2 * nj],     qf[kc], b0);
                mma_f16(S[2 * nj + 1], qf[kc], b1);
            }
        }

#pragma unroll
        for (int ni = 0; ni < 16; ni++)
#pragma unroll
            for (int r = 0; r < 4; r++) S[ni][r] *= scale;

        if (j0 == i0) {   // diagonal tile: causal mask
#pragma unroll
            for (int ni = 0; ni < 16; ni++) {
                const int col = j0 + ni * 8 + 2 * tq;
                if (col     > row0) S[ni][0] = -1e30f;
                if (col + 1 > row0) S[ni][1] = -1e30f;
                if (col     > row1) S[ni][2] = -1e30f;
                if (col + 1 > row1) S[ni][3] = -1e30f;
            }
        }

        // online softmax
        float rm0 = -INFINITY, rm1 = -INFINITY;
#pragma unroll
        for (int ni = 0; ni < 16; ni++) {
            rm0 = fmaxf(rm0, fmaxf(S[ni][0], S[ni][1]));
            rm1 = fmaxf(rm1, fmaxf(S[ni][2], S[ni][3]));
        }
        rm0 = fmaxf(rm0, __shfl_xor_sync(0xffffffffu, rm0, 1));
        rm0 = fmaxf(rm0, __shfl_xor_sync(0xffffffffu, rm0, 2));
        rm1 = fmaxf(rm1, __shfl_xor_sync(0xffffffffu, rm1, 1));
        rm1 = fmaxf(rm1, __shfl_xor_sync(0xffffffffu, rm1, 2));

        const float mn0 = fmaxf(m0, rm0);
        const float mn1 = fmaxf(m1, rm1);
        const float a0 = __expf(m0 - mn0);
        const float a1 = __expf(m1 - mn1);
        m0 = mn0; m1 = mn1;

        float rs0 = 0.0f, rs1 = 0.0f;
#pragma unroll
        for (int ni = 0; ni < 16; ni++) {
            S[ni][0] = __expf(S[ni][0] - mn0);
            S[ni][1] = __expf(S[ni][1] - mn0);
            S[ni][2] = __expf(S[ni][2] - mn1);
            S[ni][3] = __expf(S[ni][3] - mn1);
            rs0 += S[ni][0] + S[ni][1];
            rs1 += S[ni][2] + S[ni][3];
        }
        rs0 += __shfl_xor_sync(0xffffffffu, rs0, 1);
        rs0 += __shfl_xor_sync(0xffffffffu, rs0, 2);
        rs1 += __shfl_xor_sync(0xffffffffu, rs1, 1);
        rs1 += __shfl_xor_sync(0xffffffffu, rs1, 2);
        l0 = l0 * a0 + rs0;
        l1 = l1 * a1 + rs1;

#pragma unroll
        for (int ni = 0; ni < 16; ni++) {
            O[ni][0] *= a0; O[ni][1] *= a0;
            O[ni][2] *= a1; O[ni][3] *= a1;
        }

        // O += P @ V : P comes straight from S registers (FA2 layout identity)
        const int lrow = (lane & 7) + 8 * ((lane >> 3) & 1);
        const int lcol = 8 * (lane >> 4);
#pragma unroll
        for (int kc = 0; kc < 8; kc++) {
            uint32_t pa[4];
            pa[0] = pack2(S[2 * kc][0],     S[2 * kc][1]);
            pa[1] = pack2(S[2 * kc][2],     S[2 * kc][3]);
            pa[2] = pack2(S[2 * kc + 1][0], S[2 * kc + 1][1]);
            pa[3] = pack2(S[2 * kc + 1][2], S[2 * kc + 1][3]);
            const __half* vrow = Vst + (kc * 16 + lrow) * KVST + lcol;
#pragma unroll
            for (int ni2 = 0; ni2 < 8; ni2++) {
                uint32_t r0, r1, r2, r3;
                ldmx4_trans(r0, r1, r2, r3, vrow + ni2 * 16);
                uint32_t b0[2] = {r0, r1}, b1[2] = {r2, r3};
                mma_f16(O[2 * ni2],     pa, b0);
                mma_f16(O[2 * ni2 + 1], pa, b1);
            }
        }
    }
#undef LOAD_KV

    // epilogue: normalize, write half attn
    const float il0 = 1.0f / l0;
    const float il1 = 1.0f / l1;
    __half* ob = o + ((size_t)b * T_DIM + i0) * QW + h * HD;
#pragma unroll
    for (int ni = 0; ni < 16; ni++) {
        *(__half2*)(ob + (size_t)(wm + g) * QW + ni * 8 + 2 * tq) =
            __floats2half2_rn(O[ni][0] * il0, O[ni][1] * il0);
        *(__half2*)(ob + (size_t)(wm + g + 8) * QW + ni * 8 + 2 * tq) =
            __floats2half2_rn(O[ni][2] * il1, O[ni][3] * il1);
    }
}

// ---------------------------------------------------------------------------
extern "C" void kernel_launch(void* const* d_in, const int* in_sizes, int n_in,
                              void* d_out, int out_size)
{
    const float* x    = (const float*)d_in[0];
    const float* cosb = (const float*)d_in[1];
    const float* sinb = (const float*)d_in[2];
    const float* Wq   = (const float*)d_in[3];
    const float* Wk   = (const float*)d_in[4];
    const float* Wv   = (const float*)d_in[5];
    const float* Wo   = (const float*)d_in[6];
    float* out = (float*)d_out;

    float *qp, *kp;
    __half *xh, *qh, *khh, *vh, *ah, *wqh, *wkh, *wvh, *woh;
    cudaGetSymbolAddress((void**)&qp, g_q);
    cudaGetSymbolAddress((void**)&kp, g_k);
    cudaGetSymbolAddress((void**)&xh, g_xh);
    cudaGetSymbolAddress((void**)&qh, g_qh);
    cudaGetSymbolAddress((void**)&khh, g_kh);
    cudaGetSymbolAddress((void**)&vh, g_vh);
    cudaGetSymbolAddress((void**)&ah, g_ah);
    cudaGetSymbolAddress((void**)&wqh, g_wqh);
    cudaGetSymbolAddress((void**)&wkh, g_wkh);
    cudaGetSymbolAddress((void**)&wvh, g_wvh);
    cudaGetSymbolAddress((void**)&woh, g_woh);

    cudaFuncSetAttribute(gemm_qkv_h, cudaFuncAttributeMaxDynamicSharedMemorySize, GH_SMEM);
    cudaFuncSetAttribute(gemm_wo_h, cudaFuncAttributeMaxDynamicSharedMemorySize, GH_SMEM);
    cudaFuncSetAttribute(flash_h16, cudaFuncAttributeMaxDynamicSharedMemorySize, FL_SMEM);

    // Pre-passes: x -> half; weights -> transposed half
    cvt_half_kernel<<<(ROWS * HID / 4 + 255) / 256, 256>>>(x, xh, ROWS * HID / 4);
    transpose_cvt_kernel<<<dim3(QW / 32, HID / 32), dim3(32, 8)>>>(Wq, wqh, HID, QW);
    transpose_cvt_kernel<<<dim3(KW / 32, HID / 32), dim3(32, 8)>>>(Wk, wkh, HID, KW);
    transpose_cvt_kernel<<<dim3(KW / 32, HID / 32), dim3(32, 8)>>>(Wv, wvh, HID, KW);
    transpose_cvt_kernel<<<dim3(HID / 32, QW / 32), dim3(32, 8)>>>(Wo, woh, QW, HID);

    // QKV projections (fp16 tensor cores)
    gemm_qkv_h<<<dim3(24, ROWS / 128), 256, GH_SMEM>>>(xh, wqh, wkh, wvh, qp, kp, vh);

    // RoPE (single launch): fp32 -> half
    {
        int tot = ROWS * (NH + NKV) * (HD / 2);
        rope_both_kernel<<<(tot + 255) / 256, 256>>>(qp, qh, kp, khh, cosb, sinb);
    }

    // Attention (fp16, FA2 register reuse)
    flash_h16<<<dim3(T_DIM / FBM, NH, B_DIM), 256, FL_SMEM>>>(qh, khh, vh, ah);

    // Output projection (fp16)
    gemm_wo_h<<<dim3(HID / 128, ROWS / 128), 256, GH_SMEM>>>(ah, woh, out);
}

// round 9
// speedup vs baseline: 7.7870x; 1.0412x over previous
#include <cuda_runtime.h>
#include <cuda_fp16.h>
#include <math.h>
#include <stdint.h>

#define B_DIM 2
#define T_DIM 2048
#define HID 2048
#define NH 16
#define NKV 4
#define HD 128
#define ROWS (B_DIM * T_DIM)          // 4096
#define QW (NH * HD)                  // 2048
#define KW (NKV * HD)                 // 512

// Scratch (device globals: allocation is forbidden)
__device__ __half g_xh[ROWS * HID];   // x in half
__device__ __half g_qh[ROWS * QW];    // Q half (post-rope)
__device__ __half g_kh[ROWS * KW];    // K half (post-rope)
__device__ __half g_vh[ROWS * KW];    // V half
__device__ __half g_ah[ROWS * QW];    // attn out half
__device__ __half g_wqh[QW * HID];    // Wq^T half [N][K]
__device__ __half g_wkh[KW * HID];
__device__ __half g_wvh[KW * HID];
__device__ __half g_woh[HID * QW];

__device__ __forceinline__ void mma_f16(float* d, const uint32_t* a, const uint32_t* b) {
    asm volatile(
        "mma.sync.aligned.m16n8k16.row.col.f32.f16.f16.f32 "
        "{%0,%1,%2,%3}, {%4,%5,%6,%7}, {%8,%9}, {%0,%1,%2,%3};"
        : "+f"(d[0]), "+f"(d[1]), "+f"(d[2]), "+f"(d[3])
        : "r"(a[0]), "r"(a[1]), "r"(a[2]), "r"(a[3]), "r"(b[0]), "r"(b[1]));
}

__device__ __forceinline__ void ldmx4(
    uint32_t& r0, uint32_t& r1, uint32_t& r2, uint32_t& r3, const void* p)
{
    uint32_t a = (uint32_t)__cvta_generic_to_shared(p);
    asm volatile("ldmatrix.sync.aligned.m8n8.x4.shared.b16 {%0,%1,%2,%3}, [%4];"
                 : "=r"(r0), "=r"(r1), "=r"(r2), "=r"(r3) : "r"(a));
}
__device__ __forceinline__ void ldmx4_trans(
    uint32_t& r0, uint32_t& r1, uint32_t& r2, uint32_t& r3, const void* p)
{
    uint32_t a = (uint32_t)__cvta_generic_to_shared(p);
    asm volatile("ldmatrix.sync.aligned.m8n8.x4.trans.shared.b16 {%0,%1,%2,%3}, [%4];"
                 : "=r"(r0), "=r"(r1), "=r"(r2), "=r"(r3) : "r"(a));
}

__device__ __forceinline__ uint32_t pack2(float a, float b) {
    __half2 h = __floats2half2_rn(a, b);
    return *(uint32_t*)&h;
}

__device__ __forceinline__ void cp16(void* dst, const void* src) {
    uint32_t d = (uint32_t)__cvta_generic_to_shared(dst);
    asm volatile("cp.async.ca.shared.global [%0], [%1], 16;" :: "r"(d), "l"(src));
}
__device__ __forceinline__ void cp_commit() { asm volatile("cp.async.commit_group;" ::); }
template<int N> __device__ __forceinline__ void cp_wait() {
    asm volatile("cp.async.wait_group %0;" :: "n"(N));
}

// ---------------------------------------------------------------------------
// Fused pre-pass: cvt x -> half, plus 4 weight transpose+cvt, in one launch.
// Grid ranges: [0,8192) cvt-x; then Wq 4096, Wk 1024, Wv 1024, Wo 4096 blocks.
// ---------------------------------------------------------------------------
#define PP_CVT_BLKS 8192
#define PP_WQ_BLKS 4096
#define PP_WK_BLKS 1024
#define PP_WV_BLKS 1024
#define PP_WO_BLKS 4096
#define PP_TOTAL (PP_CVT_BLKS + PP_WQ_BLKS + PP_WK_BLKS + PP_WV_BLKS + PP_WO_BLKS)

__global__ __launch_bounds__(256) void prepass_kernel(
    const float* __restrict__ x,
    const float* __restrict__ Wq, const float* __restrict__ Wk,
    const float* __restrict__ Wv, const float* __restrict__ Wo,
    __half* __restrict__ xh,
    __half* __restrict__ wqh, __half* __restrict__ wkh,
    __half* __restrict__ wvh, __half* __restrict__ woh)
{
    int bid = blockIdx.x;
    const int tid = threadIdx.x;

    if (bid < PP_CVT_BLKS) {
        int i = bid * 256 + tid;               // float4 index
        float4 v = ((const float4*)x)[i];
        ((__half2*)xh)[2 * i]     = __floats2half2_rn(v.x, v.y);
        ((__half2*)xh)[2 * i + 1] = __floats2half2_rn(v.z, v.w);
        return;
    }
    bid -= PP_CVT_BLKS;

    const float* in; __half* out; int K, N;
    if (bid < PP_WQ_BLKS)                       { in = Wq; out = wqh; K = HID; N = QW; }
    else if (bid < PP_WQ_BLKS + PP_WK_BLKS)     { bid -= PP_WQ_BLKS; in = Wk; out = wkh; K = HID; N = KW; }
    else if (bid < PP_WQ_BLKS + 2 * PP_WK_BLKS) { bid -= PP_WQ_BLKS + PP_WK_BLKS; in = Wv; out = wvh; K = HID; N = KW; }
    else                                        { bid -= PP_WQ_BLKS + 2 * PP_WK_BLKS; in = Wo; out = woh; K = QW; N = HID; }

    __shared__ float tile[32][33];
    const int nbx = N / 32;
    const int n0 = (bid % nbx) * 32;
    const int k0 = (bid / nbx) * 32;
    const int tx = tid & 31, ty = tid >> 5;     // 32 x 8
#pragma unroll
    for (int i = ty; i < 32; i += 8)
        tile[i][tx] = in[(size_t)(k0 + i) * N + n0 + tx];
    __syncthreads();
#pragma unroll
    for (int i = ty; i < 32; i += 8)
        out[(size_t)(n0 + i) * K + k0 + tx] = __float2half_rn(tile[tx][i]);
}

// ---------------------------------------------------------------------------
// fp16 GEMM core: C[128 @bm][128 @bn] = A[*,2048] @ Bt[*,2048]^T
// ldmatrix fragment loads. BK=32, 3-stage cp.async. 8 warps (2x4), 64x32.
// mode 0: fp32 out; mode 1: half out; mode 2: half out with fused RoPE
// (block's 128-col tile == one head; (d, d+64) pairs staged via smem).
// ---------------------------------------------------------------------------
#define HST 40
#define HA_STG (128 * HST)            // halves
#define GH_SMEM (3 * 2 * HA_STG * 2)  // 61440 B
#define SMST 136                      // epilogue scratch stride (halves)

__device__ __forceinline__ void gemm_h_core(
    const __half* __restrict__ A, const __half* __restrict__ Bt,
    float* __restrict__ Cf, __half* __restrict__ Ch,
    int ldc, int bm, int bn, int mode,
    const float* __restrict__ cosb, const float* __restrict__ sinb,
    __half* smh)
{
    __half* Ash = smh;
    __half* Bsh = smh + 3 * HA_STG;
    const int tid = threadIdx.x, lane = tid & 31, warp = tid >> 5;
    const int g = lane >> 2, tq = lane & 3;
    const int wm = (warp >> 2) * 64, wn = (warp & 3) * 32;
    const int lr = lane & 15;               // ldmatrix row within 16
    const int lc = (lane >> 4) * 8;         // ldmatrix k-offset

    float acc[4][4][4];
#pragma unroll
    for (int mi = 0; mi < 4; mi++)
#pragma unroll
        for (int ni = 0; ni < 4; ni++)
#pragma unroll
            for (int r = 0; r < 4; r++) acc[mi][ni][r] = 0.0f;

#define LOAD_STAGE(st, k0) { \
    __half* Ad = Ash + (st) * HA_STG; \
    __half* Bd = Bsh + (st) * HA_STG; \
    _Pragma("unroll") \
    for (int j = 0; j < 2; j++) { \
        int i = tid + 256 * j; int row = i >> 2; int c = i & 3; \
        cp16(Ad + row * HST + c * 8, A + (size_t)(bm + row) * HID + (k0) + c * 8); \
        cp16(Bd + row * HST + c * 8, Bt + (size_t)(bn + row) * HID + (k0) + c * 8); \
    } \
    cp_commit(); }

    LOAD_STAGE(0, 0)
    LOAD_STAGE(1, 32)

    const int NT = HID / 32;   // 64
    for (int t = 0; t < NT; t++) {
        if (t == NT - 1) cp_wait<0>(); else cp_wait<1>();
        __syncthreads();
        if (t + 2 < NT) LOAD_STAGE((t + 2) % 3, (t + 2) * 32)

        const __half* Ast = Ash + (t % 3) * HA_STG;
        const __half* Bst = Bsh + (t % 3) * HA_STG;
#pragma unroll
        for (int ks = 0; ks < 2; ks++) {
            const int kh = ks * 16 + lc;
            uint32_t af[4][4], bf[4][2];
#pragma unroll
            for (int mi = 0; mi < 4; mi++)
                ldmx4(af[mi][0], af[mi][1], af[mi][2], af[mi][3],
                      Ast + (wm + mi * 16 + lr) * HST + kh);
#pragma unroll
            for (int nj = 0; nj < 2; nj++) {
                uint32_t r0, r1, r2, r3;
                ldmx4(r0, r1, r2, r3, Bst + (wn + nj * 16 + lr) * HST + kh);
                bf[2 * nj][0] = r0;     bf[2 * nj][1] = r2;
                bf[2 * nj + 1][0] = r1; bf[2 * nj + 1][1] = r3;
            }
#pragma unroll
            for (int mi = 0; mi < 4; mi++)
#pragma unroll
                for (int ni = 0; ni < 4; ni++)
                    mma_f16(acc[mi][ni], af[mi], bf[ni]);
        }
    }
#undef LOAD_STAGE

    if (mode == 2) {
        // stage acc to smem (half), then fused RoPE + half store
        __half* Sm = smh;   // 128 x SMST halves = 34816 B (< GH_SMEM)
        __syncthreads();    // all warps done reading pipeline stages
#pragma unroll
        for (int mi = 0; mi < 4; mi++) {
#pragma unroll
            for (int ni = 0; ni < 4; ni++) {
                const int rl = wm + mi * 16 + g;
                const int cl = wn + ni * 8 + 2 * tq;
                *(__half2*)&Sm[rl * SMST + cl] =
                    __floats2half2_rn(acc[mi][ni][0], acc[mi][ni][1]);
                *(__half2*)&Sm[(rl + 8) * SMST + cl] =
                    __floats2half2_rn(acc[mi][ni][2], acc[mi][ni][3]);
            }
        }
        __syncthreads();

        const int r0 = tid >> 3;          // 0..31
        const int d0 = (tid & 7) * 8;     // 0..56  (d in [0,64))
#pragma unroll
        for (int pass = 0; pass < 4; pass++) {
            const int row = pass * 32 + r0;
            const int grow = bm + row;
            const int tpos = grow & (T_DIM - 1);
            const float* cb = cosb + tpos * HD;
            const float* sb = sinb + tpos * HD;
            __half* dst = Ch + (size_t)grow * ldc + bn;
            const __half* src = Sm + row * SMST;
#pragma unroll
            for (int j = 0; j < 8; j += 2) {
                const int d = d0 + j;
                float x1a = __half2float(src[d]);
                float x1b = __half2float(src[d + 1]);
                float x2a = __half2float(src[d + 64]);
                float x2b = __half2float(src[d + 65]);
                float o1a = x1a * cb[d]      - x2a * sb[d];
                float o1b = x1b * cb[d + 1]  - x2b * sb[d + 1];
                float o2a = x2a * cb[d + 64] + x1a * sb[d + 64];
                float o2b = x2b * cb[d + 65] + x1b * sb[d + 65];
                *(__half2*)&dst[d]      = __floats2half2_rn(o1a, o1b);
                *(__half2*)&dst[d + 64] = __floats2half2_rn(o2a, o2b);
            }
        }
        return;
    }

#pragma unroll
    for (int mi = 0; mi < 4; mi++) {
#pragma unroll
        for (int ni = 0; ni < 4; ni++) {
            const int row = bm + wm + mi * 16 + g;
            const int col = bn + wn + ni * 8 + 2 * tq;
            if (mode == 1) {
                *(__half2*)&Ch[(size_t)row * ldc + col] =
                    __floats2half2_rn(acc[mi][ni][0], acc[mi][ni][1]);
                *(__half2*)&Ch[(size_t)(row + 8) * ldc + col] =
                    __floats2half2_rn(acc[mi][ni][2], acc[mi][ni][3]);
            } else {
                *(float2*)&Cf[(size_t)row * ldc + col] =
                    make_float2(acc[mi][ni][0], acc[mi][ni][1]);
                *(float2*)&Cf[(size_t)(row + 8) * ldc + col] =
                    make_float2(acc[mi][ni][2], acc[mi][ni][3]);
            }
        }
    }
}

// Fused QKV: bx 0..15 -> Q (half+rope), 16..19 -> K (half+rope), 20..23 -> V (half)
__global__ __launch_bounds__(256, 2) void gemm_qkv_h(
    const __half* __restrict__ x,
    const __half* __restrict__ WqT, const __half* __restrict__ WkT,
    const __half* __restrict__ WvT,
    __half* __restrict__ qp, __half* __restrict__ kp, __half* __restrict__ vp,
    const float* __restrict__ cosb, const float* __restrict__ sinb)
{
    extern __shared__ __half smh[];
    const int bx = blockIdx.x;
    const __half* Bt; __half* Ch; int ldc; int bn; int mode;
    if (bx < 16)      { Bt = WqT; Ch = qp; ldc = QW; bn = bx * 128; mode = 2; }
    else if (bx < 20) { Bt = WkT; Ch = kp; ldc = KW; bn = (bx - 16) * 128; mode = 2; }
    else              { Bt = WvT; Ch = vp; ldc = KW; bn = (bx - 20) * 128; mode = 1; }
    gemm_h_core(x, Bt, nullptr, Ch, ldc, blockIdx.y * 128, bn, mode, cosb, sinb, smh);
}

__global__ __launch_bounds__(256, 2) void gemm_wo_h(
    const __half* __restrict__ A, const __half* __restrict__ WoT,
    float* __restrict__ C)
{
    extern __shared__ __half smh[];
    gemm_h_core(A, WoT, C, nullptr, HID, blockIdx.y * 128, blockIdx.x * 128, 0,
                nullptr, nullptr, smh);
}

// ---------------------------------------------------------------------------
// fp16 flash attention, FA2-style register P reuse (no P smem, one sync/tile).
// BM=128 (8 warps x m16), BN=128, double-buffered K/V in smem.
// ---------------------------------------------------------------------------
#define FBM 128
#define FBN 128
#define KVST 136                       // halves per K/V row
#define KV_STG (128 * KVST)            // halves per stage
#define FL_SMEM (4 * KV_STG * 2)       // 139264 B

__global__ __launch_bounds__(256, 1) void flash_h16(
    const __half* __restrict__ q, const __half* __restrict__ k,
    const __half* __restrict__ v, __half* __restrict__ o)
{
    extern __shared__ __half smh[];
    __half* Ks = smh;                  // [2][128][136]
    __half* Vs = Ks + 2 * KV_STG;      // [2][128][136]

    const int tid  = threadIdx.x;
    const int lane = tid & 31;
    const int warp = tid >> 5;
    const int g = lane >> 2;
    const int tq = lane & 3;
    const int wm = warp * 16;
    const int lr = lane & 15;
    const int lc = (lane >> 4) * 8;
    const int i0 = (gridDim.x - 1 - (int)blockIdx.x) * FBM;   // heavy CTAs first
    const int h  = blockIdx.y;
    const int b  = blockIdx.z;
    const int kh = h >> 2;

    const __half* qbase = q + ((size_t)b * T_DIM + i0) * QW + h * HD;
    const __half* kbase = k + ((size_t)b * T_DIM) * KW + kh * HD;
    const __half* vbase = v + ((size_t)b * T_DIM) * KW + kh * HD;

    const float scale = 0.08838834764831845f;   // 1/sqrt(128)

    // Q fragments: 8 k16-chunks covering d=128
    uint32_t qf[8][4];
    {
        const __half* q0 = qbase + (size_t)(wm + g) * QW;
        const __half* q8 = q0 + (size_t)8 * QW;
#pragma unroll
        for (int kc = 0; kc < 8; kc++) {
            const int c = kc * 16 + 2 * tq;
            qf[kc][0] = *(const uint32_t*)(q0 + c);
            qf[kc][1] = *(const uint32_t*)(q8 + c);
            qf[kc][2] = *(const uint32_t*)(q0 + c + 8);
            qf[kc][3] = *(const uint32_t*)(q8 + c + 8);
        }
    }

    float O[16][4];
#pragma unroll
    for (int ni = 0; ni < 16; ni++)
#pragma unroll
        for (int r = 0; r < 4; r++) O[ni][r] = 0.0f;
    float m0 = -INFINITY, m1 = -INFINITY, l0 = 0.0f, l1 = 0.0f;

    const int row0 = i0 + wm + g;
    const int row1 = row0 + 8;

#define LOAD_KV(st, j0) { \
    __half* Kd = Ks + (st) * KV_STG; \
    __half* Vd = Vs + (st) * KV_STG; \
    _Pragma("unroll") \
    for (int j = 0; j < 8; j++) { \
        int i = tid + 256 * j; int row = i >> 4; int c = i & 15; \
        cp16(Kd + row * KVST + c * 8, kbase + (size_t)((j0) + row) * KW + c * 8); \
        cp16(Vd + row * KVST + c * 8, vbase + (size_t)((j0) + row) * KW + c * 8); \
    } \
    cp_commit(); }

    const int ntiles = i0 / FBN + 1;
    LOAD_KV(0, 0)

    for (int jt = 0; jt < ntiles; jt++) {
        const int j0 = jt * FBN;
        cp_wait<0>();
        __syncthreads();
        if (jt + 1 < ntiles) LOAD_KV((jt + 1) & 1, j0 + FBN)

        const __half* Kst = Ks + (jt & 1) * KV_STG;
        const __half* Vst = Vs + (jt & 1) * KV_STG;

        // S = Q @ K^T : 8 k16-chunks x 16 n8-tiles (K frags via ldmatrix)
        float S[16][4];
#pragma unroll
        for (int ni = 0; ni < 16; ni++)
#pragma unroll
            for (int r = 0; r < 4; r++) S[ni][r] = 0.0f;

#pragma unroll
        for (int kc = 0; kc < 8; kc++) {
#pragma unroll
            for (int nj = 0; nj < 8; nj++) {
                uint32_t r0, r1, r2, r3;
                ldmx4(r0, r1, r2, r3,
                      Kst + (nj * 16 + lr) * KVST + kc * 16 + lc);
                uint32_t b0[2] = {r0, r2}, b1[2] = {r1, r3};
                mma_f16(S[2 * nj],     qf[kc], b0);
                mma_f16(S[2 * nj + 1], qf[kc], b1);
            }
        }

#pragma unroll
        for (int ni = 0; ni < 16; ni++)
#pragma unroll
            for (int r = 0; r < 4; r++) S[ni][r] *= scale;

        if (j0 == i0) {   // diagonal tile: causal mask
#pragma unroll
            for (int ni = 0; ni < 16; ni++) {
                const int col = j0 + ni * 8 + 2 * tq;
                if (col     > row0) S[ni][0] = -1e30f;
                if (col + 1 > row0) S[ni][1] = -1e30f;
                if (col     > row1) S[ni][2] = -1e30f;
                if (col + 1 > row1) S[ni][3] = -1e30f;
            }
        }

        // online softmax
        float rm0 = -INFINITY, rm1 = -INFINITY;
#pragma unroll
        for (int ni = 0; ni < 16; ni++) {
            rm0 = fmaxf(rm0, fmaxf(S[ni][0], S[ni][1]));
            rm1 = fmaxf(rm1, fmaxf(S[ni][2], S[ni][3]));
        }
        rm0 = fmaxf(rm0, __shfl_xor_sync(0xffffffffu, rm0, 1));
        rm0 = fmaxf(rm0, __shfl_xor_sync(0xffffffffu, rm0, 2));
        rm1 = fmaxf(rm1, __shfl_xor_sync(0xffffffffu, rm1, 1));
        rm1 = fmaxf(rm1, __shfl_xor_sync(0xffffffffu, rm1, 2));

        const float mn0 = fmaxf(m0, rm0);
        const float mn1 = fmaxf(m1, rm1);
        const float a0 = __expf(m0 - mn0);
        const float a1 = __expf(m1 - mn1);
        m0 = mn0; m1 = mn1;

        float rs0 = 0.0f, rs1 = 0.0f;
#pragma unroll
        for (int ni = 0; ni < 16; ni++) {
            S[ni][0] = __expf(S[ni][0] - mn0);
            S[ni][1] = __expf(S[ni][1] - mn0);
            S[ni][2] = __expf(S[ni][2] - mn1);
            S[ni][3] = __expf(S[ni][3] - mn1);
            rs0 += S[ni][0] + S[ni][1];
            rs1 += S[ni][2] + S[ni][3];
        }
        rs0 += __shfl_xor_sync(0xffffffffu, rs0, 1);
        rs0 += __shfl_xor_sync(0xffffffffu, rs0, 2);
        rs1 += __shfl_xor_sync(0xffffffffu, rs1, 1);
        rs1 += __shfl_xor_sync(0xffffffffu, rs1, 2);
        l0 = l0 * a0 + rs0;
        l1 = l1 * a1 + rs1;

#pragma unroll
        for (int ni = 0; ni < 16; ni++) {
            O[ni][0] *= a0; O[ni][1] *= a0;
            O[ni][2] *= a1; O[ni][3] *= a1;
        }

        // O += P @ V : P comes straight from S registers (FA2 layout identity)
        const int lrow = (lane & 7) + 8 * ((lane >> 3) & 1);
        const int lcol = 8 * (lane >> 4);
#pragma unroll
        for (int kc = 0; kc < 8; kc++) {
            uint32_t pa[4];
            pa[0] = pack2(S[2 * kc][0],     S[2 * kc][1]);
            pa[1] = pack2(S[2 * kc][2],     S[2 * kc][3]);
            pa[2] = pack2(S[2 * kc + 1][0], S[2 * kc + 1][1]);
            pa[3] = pack2(S[2 * kc + 1][2], S[2 * kc + 1][3]);
            const __half* vrow = Vst + (kc * 16 + lrow) * KVST + lcol;
#pragma unroll
            for (int ni2 = 0; ni2 < 8; ni2++) {
                uint32_t r0, r1, r2, r3;
                ldmx4_trans(r0, r1, r2, r3, vrow + ni2 * 16);
                uint32_t b0[2] = {r0, r1}, b1[2] = {r2, r3};
                mma_f16(O[2 * ni2],     pa, b0);
                mma_f16(O[2 * ni2 + 1], pa, b1);
            }
        }
    }
#undef LOAD_KV

    // epilogue: normalize, write half attn
    const float il0 = 1.0f / l0;
    const float il1 = 1.0f / l1;
    __half* ob = o + ((size_t)b * T_DIM + i0) * QW + h * HD;
#pragma unroll
    for (int ni = 0; ni < 16; ni++) {
        *(__half2*)(ob + (size_t)(wm + g) * QW + ni * 8 + 2 * tq) =
            __floats2half2_rn(O[ni][0] * il0, O[ni][1] * il0);
        *(__half2*)(ob + (size_t)(wm + g + 8) * QW + ni * 8 + 2 * tq) =
            __floats2half2_rn(O[ni][2] * il1, O[ni][3] * il1);
    }
}

// ---------------------------------------------------------------------------
extern "C" void kernel_launch(void* const* d_in, const int* in_sizes, int n_in,
                              void* d_out, int out_size)
{
    const float* x    = (const float*)d_in[0];
    const float* cosb = (const float*)d_in[1];
    const float* sinb = (const float*)d_in[2];
    const float* Wq   = (const float*)d_in[3];
    const float* Wk   = (const float*)d_in[4];
    const float* Wv   = (const float*)d_in[5];
    const float* Wo   = (const float*)d_in[6];
    float* out = (float*)d_out;

    __half *xh, *qh, *khh, *vh, *ah, *wqh, *wkh, *wvh, *woh;
    cudaGetSymbolAddress((void**)&xh, g_xh);
    cudaGetSymbolAddress((void**)&qh, g_qh);
    cudaGetSymbolAddress((void**)&khh, g_kh);
    cudaGetSymbolAddress((void**)&vh, g_vh);
    cudaGetSymbolAddress((void**)&ah, g_ah);
    cudaGetSymbolAddress((void**)&wqh, g_wqh);
    cudaGetSymbolAddress((void**)&wkh, g_wkh);
    cudaGetSymbolAddress((void**)&wvh, g_wvh);
    cudaGetSymbolAddress((void**)&woh, g_woh);

    cudaFuncSetAttribute(gemm_qkv_h, cudaFuncAttributeMaxDynamicSharedMemorySize, GH_SMEM);
    cudaFuncSetAttribute(gemm_wo_h, cudaFuncAttributeMaxDynamicSharedMemorySize, GH_SMEM);
    cudaFuncSetAttribute(flash_h16, cudaFuncAttributeMaxDynamicSharedMemorySize, FL_SMEM);

    // Fused pre-pass: x->half and 4 weight transposes in one launch
    prepass_kernel<<<PP_TOTAL, 256>>>(x, Wq, Wk, Wv, Wo, xh, wqh, wkh, wvh, woh);

    // QKV projections with fused RoPE (Q,K) / direct half (V)
    gemm_qkv_h<<<dim3(24, ROWS / 128), 256, GH_SMEM>>>(
        xh, wqh, wkh, wvh, qh, khh, vh, cosb, sinb);

    // Attention (fp16, FA2 register reuse)
    flash_h16<<<dim3(T_DIM / FBM, NH, B_DIM), 256, FL_SMEM>>>(qh, khh, vh, ah);

    // Output projection (fp16)
    gemm_wo_h<<<dim3(HID / 128, ROWS / 128), 256, GH_SMEM>>>(ah, woh, out);
}